// round 9
// baseline (speedup 1.0000x reference)
#include <cuda_runtime.h>
#include <cuda_fp16.h>
#include <stdint.h>
#include <math.h>

#define BATCH 8
#define SEQ   2048
#define DIM   1024
#define MTOT  (BATCH * SEQ)

// ---------------------------------------------------------------------------
// Static device scratch (allocation-free contract).
// ---------------------------------------------------------------------------
__device__ __align__(256) __half g_xH[(size_t)MTOT * DIM];
__device__ __align__(256) __half g_WtH[4][(size_t)DIM * DIM];
__device__ __align__(256) __half g_Q[(size_t)MTOT * DIM];
__device__ __align__(256) __half g_K[(size_t)MTOT * DIM];
__device__ __align__(256) __half g_V[(size_t)MTOT * DIM];
__device__ __align__(256) __half g_Vt[(size_t)MTOT * DIM];
__device__ __align__(256) __half g_O[(size_t)MTOT * DIM];
__device__ __align__(256) float  g_S[(size_t)BATCH * SEQ * SEQ];
__device__ __align__(256) __half g_P[(size_t)BATCH * SEQ * SEQ];

// ---------------------------------------------------------------------------
// Helpers (arch-agnostic PTX only: cp.async / ldmatrix / mma.sync)
// ---------------------------------------------------------------------------
__device__ __forceinline__ uint32_t smem_to_u32(const void* smem_ptr) {
    uint32_t addr;
    asm("{ .reg .u64 tmp; cvta.to.shared.u64 tmp, %1; cvt.u32.u64 %0, tmp; }"
        : "=r"(addr) : "l"(smem_ptr));
    return addr;
}
#define SMEM_SWIZZLE_128B(byte_offset) \
    ((byte_offset) ^ (((byte_offset) >> 3) & 0x70))
#define CP_ASYNC_16(dst_u32, src_ptr) \
    asm volatile("cp.async.cg.shared.global [%0], [%1], 16;" \
                 :: "r"(dst_u32), "l"(src_ptr) : "memory")
#define CP_COMMIT() asm volatile("cp.async.commit_group;" ::: "memory")
#define CP_WAIT(n)  asm volatile("cp.async.wait_group %0;" :: "n"(n) : "memory")

#define LDMATRIX_X4(r0, r1, r2, r3, addr) \
    asm volatile("ldmatrix.sync.aligned.m8n8.x4.shared.b16 {%0,%1,%2,%3}, [%4];" \
                 : "=r"(r0), "=r"(r1), "=r"(r2), "=r"(r3) : "r"(addr))

#define MMA_F16(c, a, b0, b1) \
    asm volatile("mma.sync.aligned.m16n8k16.row.col.f32.f16.f16.f32 " \
                 "{%0,%1,%2,%3}, {%4,%5,%6,%7}, {%8,%9}, {%0,%1,%2,%3};" \
                 : "+f"((c)[0]), "+f"((c)[1]), "+f"((c)[2]), "+f"((c)[3]) \
                 : "r"((a)[0]), "r"((a)[1]), "r"((a)[2]), "r"((a)[3]), \
                   "r"(b0), "r"(b1))

// ---------------------------------------------------------------------------
// GEMM: D[M,N] = A@B^T, single-pass fp16 inputs, fp32 accumulate.
//   A: [M,K] K-major fp16 ; B: [N,K] K-major fp16
// CTA tile 128(M) x 256(N), BK=64 (128B rows, SW128).
// 8 warps in 2(m) x 4(n) grid, warp tile 64x64 -> 128 B smem per MMA
// (A tile read 4x, B tile read 2x). 4-stage cp.async pipeline, single
// __syncthreads per iter (wait_group(2) => tile i landed; issue i+3 after
// the barrier is safe: its buffer was consumed at iter i-1).
// EPI: 0 = fp32 out, 1 = fp32 + bias, 2 = fp16 out.
// MULTI_B: blockIdx.z selects weight set / output via pointer tables.
// ---------------------------------------------------------------------------
#define TILE_A_BYTES 16384          // 128 rows x 128B
#define TILE_B_BYTES 32768          // 256 rows x 128B
#define STAGE_BYTES  (TILE_A_BYTES + TILE_B_BYTES)   // 49152
#define STAGES 4
#define SM_TOTAL (STAGES * STAGE_BYTES)              // 196608

template <int EPI, bool MULTI_B>
__global__ void __launch_bounds__(256)
gemmh_kernel(const __half* __restrict__ A, const __half* __restrict__ B,
             float* __restrict__ Cf, __half* __restrict__ Ch,
             __half* const* __restrict__ multiCh,
             const float* __restrict__ bias,
             int K, int ldC, size_t sA, size_t sB, size_t sC)
{
    extern __shared__ char smem[];
    const uint32_t smem_u = smem_to_u32(smem);
    const int tid = threadIdx.x;
    const int lane = tid & 31;
    const int wid = tid >> 5;
    const int warp_m = wid & 1;          // 2 warps down M (64 rows each)
    const int warp_n = wid >> 1;         // 4 warps across N (64 cols each)
    const int rowBase = blockIdx.y * 128;
    const int colBase = blockIdx.x * 256;
    const size_t zA = MULTI_B ? 0 : (size_t)blockIdx.z * sA;
    const size_t zB = (size_t)blockIdx.z * sB;
    const size_t zC = MULTI_B ? 0 : (size_t)blockIdx.z * sC;
    __half* ChSel = MULTI_B ? multiCh[blockIdx.z] : Ch;

    const int ldr_row0 = tid >> 3;       // 0..31
    const int ldr_ch   = tid & 7;

    float acc[4][8][4];
#pragma unroll
    for (int i = 0; i < 4; i++)
#pragma unroll
        for (int j = 0; j < 8; j++)
#pragma unroll
            for (int e = 0; e < 4; e++) acc[i][j][e] = 0.0f;

    const int nIter = K >> 6;

    auto issue_load = [&](int i) {
        const int stage = i & 3;         // STAGES = 4
        const int kk = i << 6;
        const __half* As = A + zA;
        const __half* Bs = B + zB;
        const uint32_t aBase = smem_u + stage * STAGE_BYTES;
        const uint32_t bBase = aBase + TILE_A_BYTES;
#pragma unroll
        for (int p = 0; p < 4; p++) {    // A: 128 rows
            const int row = ldr_row0 + p * 32;
            const uint32_t soff = SMEM_SWIZZLE_128B((uint32_t)row * 128 + ldr_ch * 16);
            CP_ASYNC_16(aBase + soff,
                        As + (size_t)(rowBase + row) * K + kk + ldr_ch * 8);
        }
#pragma unroll
        for (int p = 0; p < 8; p++) {    // B: 256 rows
            const int row = ldr_row0 + p * 32;
            const uint32_t soff = SMEM_SWIZZLE_128B((uint32_t)row * 128 + ldr_ch * 16);
            CP_ASYNC_16(bBase + soff,
                        Bs + (size_t)(colBase + row) * K + kk + ldr_ch * 8);
        }
        CP_COMMIT();
    };

    // Prologue: tiles 0,1,2 in flight (groups 0,1,2)
    issue_load(0);
    issue_load(1);
    issue_load(2);

    for (int i = 0; i < nIter; i++) {
        CP_WAIT(2);                 // <=2 groups pending -> tile i landed
        __syncthreads();            // all warps finished compute of iter i-1
        if (i + 3 < nIter) issue_load(i + 3);
        else               CP_COMMIT();   // keep group numbering exact

        const uint32_t aBase = smem_u + (i & 3) * STAGE_BYTES;
        const uint32_t bBase = aBase + TILE_A_BYTES;
#pragma unroll
        for (int ks = 0; ks < 4; ks++) {
            const uint32_t k2 = ks * 32;
            uint32_t a[4][4];
            uint32_t b[4][4];
#pragma unroll
            for (int fm = 0; fm < 4; fm++) {
                const uint32_t row = warp_m * 64 + fm * 16 + (lane & 15);
                const uint32_t addr = aBase +
                    SMEM_SWIZZLE_128B(row * 128 + k2 + ((lane >> 4) << 4));
                LDMATRIX_X4(a[fm][0], a[fm][1], a[fm][2], a[fm][3], addr);
            }
#pragma unroll
            for (int fn2 = 0; fn2 < 4; fn2++) {
                const uint32_t n = warp_n * 64 + fn2 * 16 + (lane & 7) + ((lane >> 4) << 3);
                const uint32_t addr = bBase +
                    SMEM_SWIZZLE_128B(n * 128 + k2 + (((lane >> 3) & 1) << 4));
                LDMATRIX_X4(b[fn2][0], b[fn2][1], b[fn2][2], b[fn2][3], addr);
            }
#pragma unroll
            for (int fm = 0; fm < 4; fm++) {
#pragma unroll
                for (int fn2 = 0; fn2 < 4; fn2++) {
                    MMA_F16(acc[fm][fn2 * 2 + 0], a[fm], b[fn2][0], b[fn2][1]);
                    MMA_F16(acc[fm][fn2 * 2 + 1], a[fm], b[fn2][2], b[fn2][3]);
                }
            }
        }
    }

    // Epilogue
    const int gid = lane >> 2;
    const int tig = lane & 3;
#pragma unroll
    for (int fm = 0; fm < 4; fm++) {
#pragma unroll
        for (int fn = 0; fn < 8; fn++) {
            const int r0 = rowBase + warp_m * 64 + fm * 16 + gid;
            const int c  = colBase + warp_n * 64 + fn * 8 + tig * 2;
            const float* ac = acc[fm][fn];
            if (EPI == 2) {
                __half2 h0 = __floats2half2_rn(ac[0], ac[1]);
                __half2 h1 = __floats2half2_rn(ac[2], ac[3]);
                *(uint32_t*)(ChSel + zC + (size_t)r0 * ldC + c)       = *(uint32_t*)&h0;
                *(uint32_t*)(ChSel + zC + (size_t)(r0 + 8) * ldC + c) = *(uint32_t*)&h1;
            } else {
                float2 v0 = make_float2(ac[0], ac[1]);
                float2 v1 = make_float2(ac[2], ac[3]);
                if (EPI == 1) {
                    const float b0 = bias[c], b1 = bias[c + 1];
                    v0.x += b0; v0.y += b1;
                    v1.x += b0; v1.y += b1;
                }
                *(float2*)(Cf + zC + (size_t)r0 * ldC + c)       = v0;
                *(float2*)(Cf + zC + (size_t)(r0 + 8) * ldC + c) = v1;
            }
        }
    }
}

// Pointer tables (device) for fused multi-output launches
__device__ __half*       g_qkvC[3];
__device__ const float*  g_wIn[4];
__global__ void init_ptrs_kernel(const float* Wq, const float* Wk,
                                 const float* Wv, const float* Wp) {
    g_qkvC[0] = g_Q; g_qkvC[1] = g_K; g_qkvC[2] = g_V;
    g_wIn[0] = Wq; g_wIn[1] = Wk; g_wIn[2] = Wv; g_wIn[3] = Wp;
}

// ---------------------------------------------------------------------------
// fp32 -> fp16 convert (elementwise)
// ---------------------------------------------------------------------------
__global__ void __launch_bounds__(256)
convert_fp16_kernel(const float* __restrict__ x, __half* __restrict__ h)
{
    size_t i = ((size_t)blockIdx.x * 256 + threadIdx.x) * 4;
    float4 v = *(const float4*)(x + i);
    __half2 a = __floats2half2_rn(v.x, v.y);
    __half2 b = __floats2half2_rn(v.z, v.w);
    *(uint2*)(h + i) = make_uint2(*(uint32_t*)&a, *(uint32_t*)&b);
}

// ---------------------------------------------------------------------------
// Transpose + convert ALL FOUR weight matrices in one launch (z selects).
// ---------------------------------------------------------------------------
__global__ void __launch_bounds__(256)
transW_all_kernel(__half* __restrict__ thB)
{
    const float* W = g_wIn[blockIdx.z];
    __half* th = thB + (size_t)blockIdx.z * DIM * DIM;
    __shared__ float t[32][33];
    const int tx = threadIdx.x, ty = threadIdx.y;
    const int x = blockIdx.x * 32 + tx;
    const int y0 = blockIdx.y * 32;
#pragma unroll
    for (int p = 0; p < 4; p++)
        t[ty + 8 * p][tx] = W[(size_t)(y0 + ty + 8 * p) * DIM + x];
    __syncthreads();
    const int ox = blockIdx.y * 32 + tx;
    const int oy0 = blockIdx.x * 32;
#pragma unroll
    for (int p = 0; p < 4; p++)
        th[(size_t)(oy0 + ty + 8 * p) * DIM + ox] = __float2half_rn(t[tx][ty + 8 * p]);
}

// ---------------------------------------------------------------------------
// Transpose fp16 per batch: V [SEQ,DIM] -> Vt [DIM,SEQ]
// ---------------------------------------------------------------------------
__global__ void __launch_bounds__(256)
transV_kernel(const __half* __restrict__ iv, __half* __restrict__ ov)
{
    __shared__ __half t0[32][33];
    const size_t zin = (size_t)blockIdx.z * SEQ * DIM;
    const int tx = threadIdx.x, ty = threadIdx.y;
    const int x = blockIdx.x * 32 + tx;
    const int y0 = blockIdx.y * 32;
#pragma unroll
    for (int p = 0; p < 4; p++)
        t0[ty + 8 * p][tx] = iv[zin + (size_t)(y0 + ty + 8 * p) * DIM + x];
    __syncthreads();
    const int ox = blockIdx.y * 32 + tx;
    const int oy0 = blockIdx.x * 32;
#pragma unroll
    for (int p = 0; p < 4; p++)
        ov[zin + (size_t)(oy0 + ty + 8 * p) * SEQ + ox] = t0[tx][ty + 8 * p];
}

// ---------------------------------------------------------------------------
// Row softmax (SEQ=2048 cols) in log2 domain; emits fp16 P
// ---------------------------------------------------------------------------
__global__ void __launch_bounds__(256)
softmax_kernel(const float* __restrict__ S, __half* __restrict__ P,
               float scale_log2e)
{
    const size_t row = blockIdx.x;
    const float* p = S + row * SEQ;
    const int tid = threadIdx.x;

    float vals[8];
    float lmax = -INFINITY;
#pragma unroll
    for (int i = 0; i < 8; i++) {
        float v = p[tid + i * 256] * scale_log2e;
        vals[i] = v;
        lmax = fmaxf(lmax, v);
    }
    __shared__ float red[8];
#pragma unroll
    for (int o = 16; o > 0; o >>= 1)
        lmax = fmaxf(lmax, __shfl_xor_sync(0xffffffffu, lmax, o));
    if ((tid & 31) == 0) red[tid >> 5] = lmax;
    __syncthreads();
    float m = red[0];
#pragma unroll
    for (int w = 1; w < 8; w++) m = fmaxf(m, red[w]);
    __syncthreads();

    float lsum = 0.0f;
#pragma unroll
    for (int i = 0; i < 8; i++) {
        vals[i] = exp2f(vals[i] - m);
        lsum += vals[i];
    }
#pragma unroll
    for (int o = 16; o > 0; o >>= 1)
        lsum += __shfl_xor_sync(0xffffffffu, lsum, o);
    if ((tid & 31) == 0) red[tid >> 5] = lsum;
    __syncthreads();
    float tot = 0.0f;
#pragma unroll
    for (int w = 0; w < 8; w++) tot += red[w];
    const float rinv = 1.0f / tot;

#pragma unroll
    for (int i = 0; i < 8; i++)
        P[row * SEQ + tid + i * 256] = __float2half_rn(vals[i] * rinv);
}

// ---------------------------------------------------------------------------
// kernel_launch
// ---------------------------------------------------------------------------
extern "C" void kernel_launch(void* const* d_in, const int* in_sizes, int n_in,
                              void* d_out, int out_size)
{
    (void)in_sizes; (void)n_in; (void)out_size;
    const float* x  = (const float*)d_in[0];
    const float* Wq = (const float*)d_in[1];
    const float* Wk = (const float*)d_in[2];
    const float* Wv = (const float*)d_in[3];
    const float* Wp = (const float*)d_in[4];
    const float* bp = (const float*)d_in[5];
    float* out = (float*)d_out;

    __half *xH, *WtH, *Q, *K, *V, *Vt, *O, *P;
    float* S;
    __half** qkvC;
    cudaGetSymbolAddress((void**)&xH, g_xH);
    cudaGetSymbolAddress((void**)&WtH, g_WtH);
    cudaGetSymbolAddress((void**)&Q, g_Q);
    cudaGetSymbolAddress((void**)&K, g_K);
    cudaGetSymbolAddress((void**)&V, g_V);
    cudaGetSymbolAddress((void**)&Vt, g_Vt);
    cudaGetSymbolAddress((void**)&O, g_O);
    cudaGetSymbolAddress((void**)&S, g_S);
    cudaGetSymbolAddress((void**)&P, g_P);
    cudaGetSymbolAddress((void**)&qkvC, g_qkvC);

    const size_t wstep = (size_t)DIM * DIM;

    cudaFuncSetAttribute(gemmh_kernel<0, false>, cudaFuncAttributeMaxDynamicSharedMemorySize, SM_TOTAL);
    cudaFuncSetAttribute(gemmh_kernel<1, false>, cudaFuncAttributeMaxDynamicSharedMemorySize, SM_TOTAL);
    cudaFuncSetAttribute(gemmh_kernel<2, false>, cudaFuncAttributeMaxDynamicSharedMemorySize, SM_TOTAL);
    cudaFuncSetAttribute(gemmh_kernel<2, true>,  cudaFuncAttributeMaxDynamicSharedMemorySize, SM_TOTAL);

    // Launch 1: pointer tables
    init_ptrs_kernel<<<1, 1>>>(Wq, Wk, Wv, Wp);

    // Launch 2: transpose + convert all four weights
    {
        dim3 g(DIM / 32, DIM / 32, 4), b(32, 8);
        transW_all_kernel<<<g, b>>>(WtH);
    }

    // Launch 3: convert x -> fp16
    convert_fp16_kernel<<<(size_t)MTOT * DIM / 1024, 256>>>(x, xH);

    // Launch 4: fused Q/K/V projections (fp16 out)
    {
        dim3 g(DIM / 256, MTOT / 128, 3);
        gemmh_kernel<2, true><<<g, 256, SM_TOTAL>>>(
            xH, WtH, nullptr, nullptr, qkvC, nullptr,
            DIM, DIM, 0, wstep, 0);
    }

    // Launch 5 (ncu target): S = Q @ K^T per batch (fp32 out)
    {
        dim3 g(SEQ / 256, SEQ / 128, BATCH);
        gemmh_kernel<0, false><<<g, 256, SM_TOTAL>>>(
            Q, K, S, nullptr, nullptr, nullptr,
            DIM, SEQ,
            (size_t)SEQ * DIM, (size_t)SEQ * DIM, (size_t)SEQ * SEQ);
    }

    // softmax (log2 domain) -> fp16 P
    softmax_kernel<<<MTOT, 256>>>(S, P, 0.03125f * 1.4426950408889634f);

    // transpose V per batch -> Vt [DIM, SEQ]
    {
        dim3 g(DIM / 32, SEQ / 32, BATCH), b(32, 8);
        transV_kernel<<<g, b>>>(V, Vt);
    }

    // O = P @ V per batch (fp16 out)
    {
        dim3 g(DIM / 256, SEQ / 128, BATCH);
        gemmh_kernel<2, false><<<g, 256, SM_TOTAL>>>(
            P, Vt, nullptr, O, nullptr, nullptr,
            SEQ, DIM,
            (size_t)SEQ * SEQ, (size_t)DIM * SEQ, (size_t)SEQ * DIM);
    }

    // out = O @ Wp^T + bp (fp32)
    {
        dim3 g(DIM / 256, MTOT / 128, 1);
        gemmh_kernel<1, false><<<g, 256, SM_TOTAL>>>(
            O, WtH + 3 * wstep, out, nullptr, nullptr, bp,
            DIM, DIM, 0, 0, 0);
    }
}

// round 10
// speedup vs baseline: 1.0971x; 1.0971x over previous
#include <cuda_runtime.h>
#include <cuda_fp16.h>
#include <stdint.h>
#include <math.h>

#define BATCH 8
#define SEQ   2048
#define DIM   1024
#define MTOT  (BATCH * SEQ)

// ---------------------------------------------------------------------------
// Static device scratch (allocation-free contract).
// ---------------------------------------------------------------------------
__device__ __align__(256) __half g_xH[(size_t)MTOT * DIM];
__device__ __align__(256) __half g_WtH[4][(size_t)DIM * DIM];
__device__ __align__(256) __half g_Q[(size_t)MTOT * DIM];
__device__ __align__(256) __half g_K[(size_t)MTOT * DIM];
__device__ __align__(256) __half g_V[(size_t)MTOT * DIM];
__device__ __align__(256) __half g_Vt[(size_t)MTOT * DIM];
__device__ __align__(256) __half g_O[(size_t)MTOT * DIM];
__device__ __align__(256) float  g_S[(size_t)BATCH * SEQ * SEQ];
__device__ __align__(256) __half g_P[(size_t)BATCH * SEQ * SEQ];

// ---------------------------------------------------------------------------
// Helpers (arch-agnostic PTX only: cp.async / ldmatrix / mma.sync)
// ---------------------------------------------------------------------------
__device__ __forceinline__ uint32_t smem_to_u32(const void* smem_ptr) {
    uint32_t addr;
    asm("{ .reg .u64 tmp; cvta.to.shared.u64 tmp, %1; cvt.u32.u64 %0, tmp; }"
        : "=r"(addr) : "l"(smem_ptr));
    return addr;
}
#define SMEM_SWIZZLE_128B(byte_offset) \
    ((byte_offset) ^ (((byte_offset) >> 3) & 0x70))
#define CP_ASYNC_16(dst_u32, src_ptr) \
    asm volatile("cp.async.cg.shared.global [%0], [%1], 16;" \
                 :: "r"(dst_u32), "l"(src_ptr) : "memory")
#define CP_COMMIT() asm volatile("cp.async.commit_group;" ::: "memory")
#define CP_WAIT(n)  asm volatile("cp.async.wait_group %0;" :: "n"(n) : "memory")

#define LDMATRIX_X4(r0, r1, r2, r3, addr) \
    asm volatile("ldmatrix.sync.aligned.m8n8.x4.shared.b16 {%0,%1,%2,%3}, [%4];" \
                 : "=r"(r0), "=r"(r1), "=r"(r2), "=r"(r3) : "r"(addr))

#define MMA_F16(c, a, b0, b1) \
    asm volatile("mma.sync.aligned.m16n8k16.row.col.f32.f16.f16.f32 " \
                 "{%0,%1,%2,%3}, {%4,%5,%6,%7}, {%8,%9}, {%0,%1,%2,%3};" \
                 : "+f"((c)[0]), "+f"((c)[1]), "+f"((c)[2]), "+f"((c)[3]) \
                 : "r"((a)[0]), "r"((a)[1]), "r"((a)[2]), "r"((a)[3]), \
                   "r"(b0), "r"(b1))

// ---------------------------------------------------------------------------
// GEMM: D[M,N] = A@B^T, single-pass fp16 inputs, fp32 accumulate.
//   A: [M,K] K-major fp16 ; B: [N,K] K-major fp16
// R8-proven config: tile 128x128, BK=64 (128B rows, SW128), 2-stage cp.async
// double buffer, 8 warps (4m x 2n), warp tile 32x64 m16n8k16, 2 CTAs/SM.
// EPI: 0 = fp32 out, 1 = fp32 + bias, 2 = fp16 out.
// MULTI_B: blockIdx.z selects weight set (B offset) and output (C0/C1/C2).
// ---------------------------------------------------------------------------
#define TILE_BYTES 16384            // 128 rows x 128B
#define STAGE_BYTES (2 * TILE_BYTES)
#define SM_TOTAL (2 * STAGE_BYTES)  // 65536

template <int EPI, bool MULTI_B>
__global__ void __launch_bounds__(256, 2)
gemmh_kernel(const __half* __restrict__ A, const __half* __restrict__ B,
             float* __restrict__ Cf, __half* __restrict__ Ch,
             __half* __restrict__ C1, __half* __restrict__ C2,
             const float* __restrict__ bias,
             int K, int ldC, size_t sA, size_t sB, size_t sC)
{
    extern __shared__ char smem[];
    const uint32_t smem_u = smem_to_u32(smem);
    const int tid = threadIdx.x;
    const int lane = tid & 31;
    const int wid = tid >> 5;
    const int warp_m = wid & 3;
    const int warp_n = wid >> 2;
    const int rowBase = blockIdx.y * 128;
    const int colBase = blockIdx.x * 128;
    const size_t zA = MULTI_B ? 0 : (size_t)blockIdx.z * sA;
    const size_t zB = (size_t)blockIdx.z * sB;
    const size_t zC = MULTI_B ? 0 : (size_t)blockIdx.z * sC;
    __half* ChSel = Ch;
    if (MULTI_B) ChSel = (blockIdx.z == 0) ? Ch : ((blockIdx.z == 1) ? C1 : C2);

    const int ldr_row0 = tid >> 3;
    const int ldr_ch   = tid & 7;

    float acc[2][8][4];
#pragma unroll
    for (int i = 0; i < 2; i++)
#pragma unroll
        for (int j = 0; j < 8; j++)
#pragma unroll
            for (int e = 0; e < 4; e++) acc[i][j][e] = 0.0f;

    const int nIter = K >> 6;

    auto issue_load = [&](int i, int stage) {
        const int kk = i << 6;
        const __half* As = A + zA;
        const __half* Bs = B + zB;
        const uint32_t aBase = smem_u + stage * STAGE_BYTES;
        const uint32_t bBase = aBase + TILE_BYTES;
#pragma unroll
        for (int p = 0; p < 4; p++) {
            const int row = ldr_row0 + p * 32;
            const uint32_t soff = SMEM_SWIZZLE_128B((uint32_t)row * 128 + ldr_ch * 16);
            CP_ASYNC_16(aBase + soff,
                        As + (size_t)(rowBase + row) * K + kk + ldr_ch * 8);
            CP_ASYNC_16(bBase + soff,
                        Bs + (size_t)(colBase + row) * K + kk + ldr_ch * 8);
        }
        CP_COMMIT();
    };

    issue_load(0, 0);

    for (int i = 0; i < nIter; i++) {
        const int stage = i & 1;
        if (i + 1 < nIter) {
            issue_load(i + 1, (i + 1) & 1);
            CP_WAIT(1);
        } else {
            CP_WAIT(0);
        }
        __syncthreads();

        const uint32_t aBase = smem_u + stage * STAGE_BYTES;
        const uint32_t bBase = aBase + TILE_BYTES;
#pragma unroll
        for (int ks = 0; ks < 4; ks++) {
            const uint32_t k2 = ks * 32;
            uint32_t a[2][4];
            uint32_t b[4][4];
#pragma unroll
            for (int fm = 0; fm < 2; fm++) {
                const uint32_t row = warp_m * 32 + fm * 16 + (lane & 15);
                const uint32_t addr = aBase +
                    SMEM_SWIZZLE_128B(row * 128 + k2 + ((lane >> 4) << 4));
                LDMATRIX_X4(a[fm][0], a[fm][1], a[fm][2], a[fm][3], addr);
            }
#pragma unroll
            for (int fn2 = 0; fn2 < 4; fn2++) {
                const uint32_t n = warp_n * 64 + fn2 * 16 + (lane & 7) + ((lane >> 4) << 3);
                const uint32_t addr = bBase +
                    SMEM_SWIZZLE_128B(n * 128 + k2 + (((lane >> 3) & 1) << 4));
                LDMATRIX_X4(b[fn2][0], b[fn2][1], b[fn2][2], b[fn2][3], addr);
            }
#pragma unroll
            for (int fn2 = 0; fn2 < 4; fn2++) {
                MMA_F16(acc[0][fn2 * 2 + 0], a[0], b[fn2][0], b[fn2][1]);
                MMA_F16(acc[0][fn2 * 2 + 1], a[0], b[fn2][2], b[fn2][3]);
                MMA_F16(acc[1][fn2 * 2 + 0], a[1], b[fn2][0], b[fn2][1]);
                MMA_F16(acc[1][fn2 * 2 + 1], a[1], b[fn2][2], b[fn2][3]);
            }
        }
        __syncthreads();
    }

    // Epilogue
    const int gid = lane >> 2;
    const int tig = lane & 3;
#pragma unroll
    for (int fm = 0; fm < 2; fm++) {
#pragma unroll
        for (int fn = 0; fn < 8; fn++) {
            const int r0 = rowBase + warp_m * 32 + fm * 16 + gid;
            const int c  = colBase + warp_n * 64 + fn * 8 + tig * 2;
            const float* ac = acc[fm][fn];
            if (EPI == 2) {
                __half2 h0 = __floats2half2_rn(ac[0], ac[1]);
                __half2 h1 = __floats2half2_rn(ac[2], ac[3]);
                *(uint32_t*)(ChSel + zC + (size_t)r0 * ldC + c)       = *(uint32_t*)&h0;
                *(uint32_t*)(ChSel + zC + (size_t)(r0 + 8) * ldC + c) = *(uint32_t*)&h1;
            } else {
                float2 v0 = make_float2(ac[0], ac[1]);
                float2 v1 = make_float2(ac[2], ac[3]);
                if (EPI == 1) {
                    const float b0 = bias[c], b1 = bias[c + 1];
                    v0.x += b0; v0.y += b1;
                    v1.x += b0; v1.y += b1;
                }
                *(float2*)(Cf + zC + (size_t)r0 * ldC + c)       = v0;
                *(float2*)(Cf + zC + (size_t)(r0 + 8) * ldC + c) = v1;
            }
        }
    }
}

// ---------------------------------------------------------------------------
// fp32 -> fp16 convert (elementwise)
// ---------------------------------------------------------------------------
__global__ void __launch_bounds__(256)
convert_fp16_kernel(const float* __restrict__ x, __half* __restrict__ h)
{
    size_t i = ((size_t)blockIdx.x * 256 + threadIdx.x) * 4;
    float4 v = *(const float4*)(x + i);
    __half2 a = __floats2half2_rn(v.x, v.y);
    __half2 b = __floats2half2_rn(v.z, v.w);
    *(uint2*)(h + i) = make_uint2(*(uint32_t*)&a, *(uint32_t*)&b);
}

// ---------------------------------------------------------------------------
// Transpose + convert ALL FOUR weight matrices in one launch (z selects,
// direct pointer args). Wq (z==0) is pre-scaled by scale*log2e so S comes
// out of the QK^T GEMM already in the log2 domain.
// ---------------------------------------------------------------------------
__global__ void __launch_bounds__(256)
transW_all_kernel(const float* __restrict__ W0, const float* __restrict__ W1,
                  const float* __restrict__ W2, const float* __restrict__ W3,
                  __half* __restrict__ thB, float qscale)
{
    const float* W = (blockIdx.z == 0) ? W0 :
                     (blockIdx.z == 1) ? W1 :
                     (blockIdx.z == 2) ? W2 : W3;
    const float sc = (blockIdx.z == 0) ? qscale : 1.0f;
    __half* th = thB + (size_t)blockIdx.z * DIM * DIM;
    __shared__ float t[32][33];
    const int tx = threadIdx.x, ty = threadIdx.y;
    const int x = blockIdx.x * 32 + tx;
    const int y0 = blockIdx.y * 32;
#pragma unroll
    for (int p = 0; p < 4; p++)
        t[ty + 8 * p][tx] = W[(size_t)(y0 + ty + 8 * p) * DIM + x];
    __syncthreads();
    const int ox = blockIdx.y * 32 + tx;
    const int oy0 = blockIdx.x * 32;
#pragma unroll
    for (int p = 0; p < 4; p++)
        th[(size_t)(oy0 + ty + 8 * p) * DIM + ox] =
            __float2half_rn(t[tx][ty + 8 * p] * sc);
}

// ---------------------------------------------------------------------------
// Transpose fp16 per batch: V [SEQ,DIM] -> Vt [DIM,SEQ]
// ---------------------------------------------------------------------------
__global__ void __launch_bounds__(256)
transV_kernel(const __half* __restrict__ iv, __half* __restrict__ ov)
{
    __shared__ __half t0[32][33];
    const size_t zin = (size_t)blockIdx.z * SEQ * DIM;
    const int tx = threadIdx.x, ty = threadIdx.y;
    const int x = blockIdx.x * 32 + tx;
    const int y0 = blockIdx.y * 32;
#pragma unroll
    for (int p = 0; p < 4; p++)
        t0[ty + 8 * p][tx] = iv[zin + (size_t)(y0 + ty + 8 * p) * DIM + x];
    __syncthreads();
    const int ox = blockIdx.y * 32 + tx;
    const int oy0 = blockIdx.x * 32;
#pragma unroll
    for (int p = 0; p < 4; p++)
        ov[zin + (size_t)(oy0 + ty + 8 * p) * SEQ + ox] = t0[tx][ty + 8 * p];
}

// ---------------------------------------------------------------------------
// Row softmax (SEQ=2048 cols); S is ALREADY in log2 domain (scale folded
// into Wq). Emits fp16 P.
// ---------------------------------------------------------------------------
__global__ void __launch_bounds__(256)
softmax_kernel(const float* __restrict__ S, __half* __restrict__ P)
{
    const size_t row = blockIdx.x;
    const float* p = S + row * SEQ;
    const int tid = threadIdx.x;

    float vals[8];
    float lmax = -INFINITY;
#pragma unroll
    for (int i = 0; i < 8; i++) {
        float v = p[tid + i * 256];
        vals[i] = v;
        lmax = fmaxf(lmax, v);
    }
    __shared__ float red[8];
#pragma unroll
    for (int o = 16; o > 0; o >>= 1)
        lmax = fmaxf(lmax, __shfl_xor_sync(0xffffffffu, lmax, o));
    if ((tid & 31) == 0) red[tid >> 5] = lmax;
    __syncthreads();
    float m = red[0];
#pragma unroll
    for (int w = 1; w < 8; w++) m = fmaxf(m, red[w]);
    __syncthreads();

    float lsum = 0.0f;
#pragma unroll
    for (int i = 0; i < 8; i++) {
        vals[i] = exp2f(vals[i] - m);
        lsum += vals[i];
    }
#pragma unroll
    for (int o = 16; o > 0; o >>= 1)
        lsum += __shfl_xor_sync(0xffffffffu, lsum, o);
    if ((tid & 31) == 0) red[tid >> 5] = lsum;
    __syncthreads();
    float tot = 0.0f;
#pragma unroll
    for (int w = 0; w < 8; w++) tot += red[w];
    const float rinv = 1.0f / tot;

#pragma unroll
    for (int i = 0; i < 8; i++)
        P[row * SEQ + tid + i * 256] = __float2half_rn(vals[i] * rinv);
}

// ---------------------------------------------------------------------------
// kernel_launch
// ---------------------------------------------------------------------------
extern "C" void kernel_launch(void* const* d_in, const int* in_sizes, int n_in,
                              void* d_out, int out_size)
{
    (void)in_sizes; (void)n_in; (void)out_size;
    const float* x  = (const float*)d_in[0];
    const float* Wq = (const float*)d_in[1];
    const float* Wk = (const float*)d_in[2];
    const float* Wv = (const float*)d_in[3];
    const float* Wp = (const float*)d_in[4];
    const float* bp = (const float*)d_in[5];
    float* out = (float*)d_out;

    __half *xH, *WtH, *Q, *K, *V, *Vt, *O, *P;
    float* S;
    cudaGetSymbolAddress((void**)&xH, g_xH);
    cudaGetSymbolAddress((void**)&WtH, g_WtH);
    cudaGetSymbolAddress((void**)&Q, g_Q);
    cudaGetSymbolAddress((void**)&K, g_K);
    cudaGetSymbolAddress((void**)&V, g_V);
    cudaGetSymbolAddress((void**)&Vt, g_Vt);
    cudaGetSymbolAddress((void**)&O, g_O);
    cudaGetSymbolAddress((void**)&S, g_S);
    cudaGetSymbolAddress((void**)&P, g_P);

    const size_t wstep = (size_t)DIM * DIM;

    cudaFuncSetAttribute(gemmh_kernel<0, false>, cudaFuncAttributeMaxDynamicSharedMemorySize, SM_TOTAL);
    cudaFuncSetAttribute(gemmh_kernel<1, false>, cudaFuncAttributeMaxDynamicSharedMemorySize, SM_TOTAL);
    cudaFuncSetAttribute(gemmh_kernel<2, false>, cudaFuncAttributeMaxDynamicSharedMemorySize, SM_TOTAL);
    cudaFuncSetAttribute(gemmh_kernel<2, true>,  cudaFuncAttributeMaxDynamicSharedMemorySize, SM_TOTAL);

    // Launch 1: transpose + convert all four weights (Wq pre-scaled)
    {
        dim3 g(DIM / 32, DIM / 32, 4), b(32, 8);
        transW_all_kernel<<<g, b>>>(Wq, Wk, Wv, Wp, WtH,
                                    0.03125f * 1.4426950408889634f);
    }

    // Launch 2: convert x -> fp16
    convert_fp16_kernel<<<(size_t)MTOT * DIM / 1024, 256>>>(x, xH);

    // Launch 3: fused Q/K/V projections (fp16 out; z selects W and output)
    {
        dim3 g(DIM / 128, MTOT / 128, 3);
        gemmh_kernel<2, true><<<g, 256, SM_TOTAL>>>(
            xH, WtH, nullptr, Q, K, V, nullptr,
            DIM, DIM, 0, wstep, 0);
    }

    // Launch 4: S = Q @ K^T per batch (fp32 out, log2-domain logits)
    {
        dim3 g(SEQ / 128, SEQ / 128, BATCH);
        gemmh_kernel<0, false><<<g, 256, SM_TOTAL>>>(
            Q, K, S, nullptr, nullptr, nullptr, nullptr,
            DIM, SEQ,
            (size_t)SEQ * DIM, (size_t)SEQ * DIM, (size_t)SEQ * SEQ);
    }

    // Launch 5: softmax -> fp16 P
    softmax_kernel<<<MTOT, 256>>>(S, P);

    // Launch 6: transpose V per batch -> Vt [DIM, SEQ]
    {
        dim3 g(DIM / 32, SEQ / 32, BATCH), b(32, 8);
        transV_kernel<<<g, b>>>(V, Vt);
    }

    // Launch 7: O = P @ V per batch (fp16 out)
    {
        dim3 g(DIM / 128, SEQ / 128, BATCH);
        gemmh_kernel<2, false><<<g, 256, SM_TOTAL>>>(
            P, Vt, nullptr, O, nullptr, nullptr, nullptr,
            SEQ, DIM,
            (size_t)SEQ * SEQ, (size_t)DIM * SEQ, (size_t)SEQ * DIM);
    }

    // Launch 8: out = O @ Wp^T + bp (fp32)
    {
        dim3 g(DIM / 128, MTOT / 128, 1);
        gemmh_kernel<1, false><<<g, 256, SM_TOTAL>>>(
            O, WtH + 3 * wstep, out, nullptr, nullptr, nullptr, bp,
            DIM, DIM, 0, 0, 0);
    }
}

// round 12
// speedup vs baseline: 1.1229x; 1.0234x over previous
#include <cuda_runtime.h>
#include <cuda_fp16.h>
#include <stdint.h>
#include <math.h>

#define BATCH 8
#define SEQ   2048
#define DIM   1024
#define MTOT  (BATCH * SEQ)

// ---------------------------------------------------------------------------
// Static device scratch (allocation-free contract).
// ---------------------------------------------------------------------------
__device__ __align__(256) __half g_xH[(size_t)MTOT * DIM];
__device__ __align__(256) __half g_WtH[4][(size_t)DIM * DIM];
__device__ __align__(256) __half g_Q[(size_t)MTOT * DIM];
__device__ __align__(256) __half g_K[(size_t)MTOT * DIM];
__device__ __align__(256) __half g_V[(size_t)MTOT * DIM];
__device__ __align__(256) __half g_Vt[(size_t)MTOT * DIM];
__device__ __align__(256) __half g_O[(size_t)MTOT * DIM];
__device__ __align__(256) float  g_S[(size_t)BATCH * SEQ * SEQ];
__device__ __align__(256) __half g_P[(size_t)BATCH * SEQ * SEQ];

// ---------------------------------------------------------------------------
// Helpers (arch-agnostic PTX only: cp.async / ldmatrix / mma.sync)
// ---------------------------------------------------------------------------
__device__ __forceinline__ uint32_t smem_to_u32(const void* smem_ptr) {
    uint32_t addr;
    asm("{ .reg .u64 tmp; cvta.to.shared.u64 tmp, %1; cvt.u32.u64 %0, tmp; }"
        : "=r"(addr) : "l"(smem_ptr));
    return addr;
}
#define SMEM_SWIZZLE_128B(byte_offset) \
    ((byte_offset) ^ (((byte_offset) >> 3) & 0x70))
#define CP_ASYNC_16(dst_u32, src_ptr) \
    asm volatile("cp.async.cg.shared.global [%0], [%1], 16;" \
                 :: "r"(dst_u32), "l"(src_ptr) : "memory")
#define CP_COMMIT() asm volatile("cp.async.commit_group;" ::: "memory")
#define CP_WAIT(n)  asm volatile("cp.async.wait_group %0;" :: "n"(n) : "memory")

#define LDMATRIX_X4(r0, r1, r2, r3, addr) \
    asm volatile("ldmatrix.sync.aligned.m8n8.x4.shared.b16 {%0,%1,%2,%3}, [%4];" \
                 : "=r"(r0), "=r"(r1), "=r"(r2), "=r"(r3) : "r"(addr))

#define MMA_F16(c, a, b0, b1) \
    asm volatile("mma.sync.aligned.m16n8k16.row.col.f32.f16.f16.f32 " \
                 "{%0,%1,%2,%3}, {%4,%5,%6,%7}, {%8,%9}, {%0,%1,%2,%3};" \
                 : "+f"((c)[0]), "+f"((c)[1]), "+f"((c)[2]), "+f"((c)[3]) \
                 : "r"((a)[0]), "r"((a)[1]), "r"((a)[2]), "r"((a)[3]), \
                   "r"(b0), "r"(b1))

// ---------------------------------------------------------------------------
// GEMM: D[M,N] = A@B^T, single-pass fp16 inputs, fp32 accumulate.
// R8-proven config: tile 128x128, BK=64 (128B rows, SW128), 2-stage cp.async
// double buffer, 8 warps (4m x 2n), warp tile 32x64 m16n8k16, 2 CTAs/SM.
// EPI: 0 = fp32 out, 1 = fp32 + bias, 2 = fp16 out.
// MULTI_B: blockIdx.z selects weight set (B offset) and output (C0/C1/C2).
// ---------------------------------------------------------------------------
#define TILE_BYTES 16384            // 128 rows x 128B
#define STAGE_BYTES (2 * TILE_BYTES)
#define SM_TOTAL (2 * STAGE_BYTES)  // 65536

template <int EPI, bool MULTI_B>
__global__ void __launch_bounds__(256, 2)
gemmh_kernel(const __half* __restrict__ A, const __half* __restrict__ B,
             float* __restrict__ Cf, __half* __restrict__ Ch,
             __half* __restrict__ C1, __half* __restrict__ C2,
             const float* __restrict__ bias,
             int K, int ldC, size_t sA, size_t sB, size_t sC)
{
    extern __shared__ char smem[];
    const uint32_t smem_u = smem_to_u32(smem);
    const int tid = threadIdx.x;
    const int lane = tid & 31;
    const int wid = tid >> 5;
    const int warp_m = wid & 3;
    const int warp_n = wid >> 2;
    const int rowBase = blockIdx.y * 128;
    const int colBase = blockIdx.x * 128;
    const size_t zA = MULTI_B ? 0 : (size_t)blockIdx.z * sA;
    const size_t zB = (size_t)blockIdx.z * sB;
    const size_t zC = MULTI_B ? 0 : (size_t)blockIdx.z * sC;
    __half* ChSel = Ch;
    if (MULTI_B) ChSel = (blockIdx.z == 0) ? Ch : ((blockIdx.z == 1) ? C1 : C2);

    const int ldr_row0 = tid >> 3;
    const int ldr_ch   = tid & 7;

    float acc[2][8][4];
#pragma unroll
    for (int i = 0; i < 2; i++)
#pragma unroll
        for (int j = 0; j < 8; j++)
#pragma unroll
            for (int e = 0; e < 4; e++) acc[i][j][e] = 0.0f;

    const int nIter = K >> 6;

    auto issue_load = [&](int i, int stage) {
        const int kk = i << 6;
        const __half* As = A + zA;
        const __half* Bs = B + zB;
        const uint32_t aBase = smem_u + stage * STAGE_BYTES;
        const uint32_t bBase = aBase + TILE_BYTES;
#pragma unroll
        for (int p = 0; p < 4; p++) {
            const int row = ldr_row0 + p * 32;
            const uint32_t soff = SMEM_SWIZZLE_128B((uint32_t)row * 128 + ldr_ch * 16);
            CP_ASYNC_16(aBase + soff,
                        As + (size_t)(rowBase + row) * K + kk + ldr_ch * 8);
            CP_ASYNC_16(bBase + soff,
                        Bs + (size_t)(colBase + row) * K + kk + ldr_ch * 8);
        }
        CP_COMMIT();
    };

    issue_load(0, 0);

    for (int i = 0; i < nIter; i++) {
        const int stage = i & 1;
        if (i + 1 < nIter) {
            issue_load(i + 1, (i + 1) & 1);
            CP_WAIT(1);
        } else {
            CP_WAIT(0);
        }
        __syncthreads();

        const uint32_t aBase = smem_u + stage * STAGE_BYTES;
        const uint32_t bBase = aBase + TILE_BYTES;
#pragma unroll
        for (int ks = 0; ks < 4; ks++) {
            const uint32_t k2 = ks * 32;
            uint32_t a[2][4];
            uint32_t b[4][4];
#pragma unroll
            for (int fm = 0; fm < 2; fm++) {
                const uint32_t row = warp_m * 32 + fm * 16 + (lane & 15);
                const uint32_t addr = aBase +
                    SMEM_SWIZZLE_128B(row * 128 + k2 + ((lane >> 4) << 4));
                LDMATRIX_X4(a[fm][0], a[fm][1], a[fm][2], a[fm][3], addr);
            }
#pragma unroll
            for (int fn2 = 0; fn2 < 4; fn2++) {
                const uint32_t n = warp_n * 64 + fn2 * 16 + (lane & 7) + ((lane >> 4) << 3);
                const uint32_t addr = bBase +
                    SMEM_SWIZZLE_128B(n * 128 + k2 + (((lane >> 3) & 1) << 4));
                LDMATRIX_X4(b[fn2][0], b[fn2][1], b[fn2][2], b[fn2][3], addr);
            }
#pragma unroll
            for (int fn2 = 0; fn2 < 4; fn2++) {
                MMA_F16(acc[0][fn2 * 2 + 0], a[0], b[fn2][0], b[fn2][1]);
                MMA_F16(acc[0][fn2 * 2 + 1], a[0], b[fn2][2], b[fn2][3]);
                MMA_F16(acc[1][fn2 * 2 + 0], a[1], b[fn2][0], b[fn2][1]);
                MMA_F16(acc[1][fn2 * 2 + 1], a[1], b[fn2][2], b[fn2][3]);
            }
        }
        __syncthreads();
    }

    // Epilogue
    const int gid = lane >> 2;
    const int tig = lane & 3;
#pragma unroll
    for (int fm = 0; fm < 2; fm++) {
#pragma unroll
        for (int fn = 0; fn < 8; fn++) {
            const int r0 = rowBase + warp_m * 32 + fm * 16 + gid;
            const int c  = colBase + warp_n * 64 + fn * 8 + tig * 2;
            const float* ac = acc[fm][fn];
            if (EPI == 2) {
                __half2 h0 = __floats2half2_rn(ac[0], ac[1]);
                __half2 h1 = __floats2half2_rn(ac[2], ac[3]);
                *(uint32_t*)(ChSel + zC + (size_t)r0 * ldC + c)       = *(uint32_t*)&h0;
                *(uint32_t*)(ChSel + zC + (size_t)(r0 + 8) * ldC + c) = *(uint32_t*)&h1;
            } else {
                float2 v0 = make_float2(ac[0], ac[1]);
                float2 v1 = make_float2(ac[2], ac[3]);
                if (EPI == 1) {
                    const float b0 = bias[c], b1 = bias[c + 1];
                    v0.x += b0; v0.y += b1;
                    v1.x += b0; v1.y += b1;
                }
                *(float2*)(Cf + zC + (size_t)r0 * ldC + c)       = v0;
                *(float2*)(Cf + zC + (size_t)(r0 + 8) * ldC + c) = v1;
            }
        }
    }
}

// ---------------------------------------------------------------------------
// fp32 -> fp16 convert (elementwise)
// ---------------------------------------------------------------------------
__global__ void __launch_bounds__(256)
convert_fp16_kernel(const float* __restrict__ x, __half* __restrict__ h)
{
    size_t i = ((size_t)blockIdx.x * 256 + threadIdx.x) * 4;
    float4 v = *(const float4*)(x + i);
    __half2 a = __floats2half2_rn(v.x, v.y);
    __half2 b = __floats2half2_rn(v.z, v.w);
    *(uint2*)(h + i) = make_uint2(*(uint32_t*)&a, *(uint32_t*)&b);
}

// ---------------------------------------------------------------------------
// Transpose + convert ALL FOUR weight matrices in one launch.
// Wq (z==0) pre-scaled by scale*log2e -> S comes out in log2 domain.
// ---------------------------------------------------------------------------
__global__ void __launch_bounds__(256)
transW_all_kernel(const float* __restrict__ W0, const float* __restrict__ W1,
                  const float* __restrict__ W2, const float* __restrict__ W3,
                  __half* __restrict__ thB, float qscale)
{
    const float* W = (blockIdx.z == 0) ? W0 :
                     (blockIdx.z == 1) ? W1 :
                     (blockIdx.z == 2) ? W2 : W3;
    const float sc = (blockIdx.z == 0) ? qscale : 1.0f;
    __half* th = thB + (size_t)blockIdx.z * DIM * DIM;
    __shared__ float t[32][33];
    const int tx = threadIdx.x, ty = threadIdx.y;
    const int x = blockIdx.x * 32 + tx;
    const int y0 = blockIdx.y * 32;
#pragma unroll
    for (int p = 0; p < 4; p++)
        t[ty + 8 * p][tx] = W[(size_t)(y0 + ty + 8 * p) * DIM + x];
    __syncthreads();
    const int ox = blockIdx.y * 32 + tx;
    const int oy0 = blockIdx.x * 32;
#pragma unroll
    for (int p = 0; p < 4; p++)
        th[(size_t)(oy0 + ty + 8 * p) * DIM + ox] =
            __float2half_rn(t[tx][ty + 8 * p] * sc);
}

// ---------------------------------------------------------------------------
// Transpose fp16 per batch: V [SEQ,DIM] -> Vt [DIM,SEQ]
// ---------------------------------------------------------------------------
__global__ void __launch_bounds__(256)
transV_kernel(const __half* __restrict__ iv, __half* __restrict__ ov)
{
    __shared__ __half t0[32][33];
    const size_t zin = (size_t)blockIdx.z * SEQ * DIM;
    const int tx = threadIdx.x, ty = threadIdx.y;
    const int x = blockIdx.x * 32 + tx;
    const int y0 = blockIdx.y * 32;
#pragma unroll
    for (int p = 0; p < 4; p++)
        t0[ty + 8 * p][tx] = iv[zin + (size_t)(y0 + ty + 8 * p) * DIM + x];
    __syncthreads();
    const int ox = blockIdx.y * 32 + tx;
    const int oy0 = blockIdx.x * 32;
#pragma unroll
    for (int p = 0; p < 4; p++)
        ov[zin + (size_t)(oy0 + ty + 8 * p) * SEQ + ox] = t0[tx][ty + 8 * p];
}

// ---------------------------------------------------------------------------
// Row softmax (SEQ=2048 cols); S is ALREADY in log2 domain. Emits fp16 P.
// ---------------------------------------------------------------------------
__global__ void __launch_bounds__(256)
softmax_kernel(const float* __restrict__ S, __half* __restrict__ P)
{
    const size_t row = blockIdx.x;
    const float* p = S + row * SEQ;
    const int tid = threadIdx.x;

    float vals[8];
    float lmax = -INFINITY;
#pragma unroll
    for (int i = 0; i < 8; i++) {
        float v = p[tid + i * 256];
        vals[i] = v;
        lmax = fmaxf(lmax, v);
    }
    __shared__ float red[8];
#pragma unroll
    for (int o = 16; o > 0; o >>= 1)
        lmax = fmaxf(lmax, __shfl_xor_sync(0xffffffffu, lmax, o));
    if ((tid & 31) == 0) red[tid >> 5] = lmax;
    __syncthreads();
    float m = red[0];
#pragma unroll
    for (int w = 1; w < 8; w++) m = fmaxf(m, red[w]);
    __syncthreads();

    float lsum = 0.0f;
#pragma unroll
    for (int i = 0; i < 8; i++) {
        vals[i] = exp2f(vals[i] - m);
        lsum += vals[i];
    }
#pragma unroll
    for (int o = 16; o > 0; o >>= 1)
        lsum += __shfl_xor_sync(0xffffffffu, lsum, o);
    if ((tid & 31) == 0) red[tid >> 5] = lsum;
    __syncthreads();
    float tot = 0.0f;
#pragma unroll
    for (int w = 0; w < 8; w++) tot += red[w];
    const float rinv = 1.0f / tot;

#pragma unroll
    for (int i = 0; i < 8; i++)
        P[row * SEQ + tid + i * 256] = __float2half_rn(vals[i] * rinv);
}

// ---------------------------------------------------------------------------
// kernel_launch — attention section split across 2 forked streams (batches
// 0-3 / 4-7): softmax/transV (memory-bound) hide under GEMMs (tensor-bound)
// and co-resident CTAs fill each other's barrier bubbles.
// Streams/events are created AND destroyed every call: by the time of the
// destroys both side streams have been joined back into the origin stream
// (event waits), so they are out of capture mode; destruction is a host-side
// op that releases their device memory, keeping the post-teardown memory
// checkpoint at baseline.
// ---------------------------------------------------------------------------
extern "C" void kernel_launch(void* const* d_in, const int* in_sizes, int n_in,
                              void* d_out, int out_size)
{
    (void)in_sizes; (void)n_in; (void)out_size;
    const float* x  = (const float*)d_in[0];
    const float* Wq = (const float*)d_in[1];
    const float* Wk = (const float*)d_in[2];
    const float* Wv = (const float*)d_in[3];
    const float* Wp = (const float*)d_in[4];
    const float* bp = (const float*)d_in[5];
    float* out = (float*)d_out;

    __half *xH, *WtH, *Q, *K, *V, *Vt, *O, *P;
    float* S;
    cudaGetSymbolAddress((void**)&xH, g_xH);
    cudaGetSymbolAddress((void**)&WtH, g_WtH);
    cudaGetSymbolAddress((void**)&Q, g_Q);
    cudaGetSymbolAddress((void**)&K, g_K);
    cudaGetSymbolAddress((void**)&V, g_V);
    cudaGetSymbolAddress((void**)&Vt, g_Vt);
    cudaGetSymbolAddress((void**)&O, g_O);
    cudaGetSymbolAddress((void**)&S, g_S);
    cudaGetSymbolAddress((void**)&P, g_P);

    const size_t wstep = (size_t)DIM * DIM;

    cudaFuncSetAttribute(gemmh_kernel<0, false>, cudaFuncAttributeMaxDynamicSharedMemorySize, SM_TOTAL);
    cudaFuncSetAttribute(gemmh_kernel<1, false>, cudaFuncAttributeMaxDynamicSharedMemorySize, SM_TOTAL);
    cudaFuncSetAttribute(gemmh_kernel<2, false>, cudaFuncAttributeMaxDynamicSharedMemorySize, SM_TOTAL);
    cudaFuncSetAttribute(gemmh_kernel<2, true>,  cudaFuncAttributeMaxDynamicSharedMemorySize, SM_TOTAL);

    // Fork plumbing — created per call, destroyed at the end of this call.
    cudaStream_t s1, s2;
    cudaEvent_t evF, e1, e2;
    cudaStreamCreateWithFlags(&s1, cudaStreamNonBlocking);
    cudaStreamCreateWithFlags(&s2, cudaStreamNonBlocking);
    cudaEventCreateWithFlags(&evF, cudaEventDisableTiming);
    cudaEventCreateWithFlags(&e1,  cudaEventDisableTiming);
    cudaEventCreateWithFlags(&e2,  cudaEventDisableTiming);

    // ---- main stream: prep + QKV ----
    {
        dim3 g(DIM / 32, DIM / 32, 4), b(32, 8);
        transW_all_kernel<<<g, b>>>(Wq, Wk, Wv, Wp, WtH,
                                    0.03125f * 1.4426950408889634f);
    }
    convert_fp16_kernel<<<(size_t)MTOT * DIM / 1024, 256>>>(x, xH);
    {
        dim3 g(DIM / 128, MTOT / 128, 3);
        gemmh_kernel<2, true><<<g, 256, SM_TOTAL>>>(
            xH, WtH, nullptr, Q, K, V, nullptr,
            DIM, DIM, 0, wstep, 0);
    }

    // ---- fork: two halves of the batch dimension ----
    cudaEventRecord(evF, 0);
    cudaStreamWaitEvent(s1, evF, 0);
    cudaStreamWaitEvent(s2, evF, 0);

    const size_t HB = 4;                       // batches per half
    const size_t qkvOff = HB * SEQ * DIM;      // fp16 elements per half
    const size_t sOff   = HB * SEQ * SEQ;      // S/P elements per half

    for (int h = 0; h < 2; h++) {
        cudaStream_t st = h ? s2 : s1;
        const size_t qo = h * qkvOff;
        const size_t so = h * sOff;

        // transV (4 batches)
        {
            dim3 g(DIM / 32, SEQ / 32, HB), b(32, 8);
            transV_kernel<<<g, b, 0, st>>>(V + qo, Vt + qo);
        }
        // S = Q @ K^T (4 batches, fp32 log2-domain logits)
        {
            dim3 g(SEQ / 128, SEQ / 128, HB);
            gemmh_kernel<0, false><<<g, 256, SM_TOTAL, st>>>(
                Q + qo, K + qo, S + so, nullptr, nullptr, nullptr, nullptr,
                DIM, SEQ,
                (size_t)SEQ * DIM, (size_t)SEQ * DIM, (size_t)SEQ * SEQ);
        }
        // softmax -> fp16 P (4 batches of rows)
        softmax_kernel<<<HB * SEQ, 256, 0, st>>>(S + so, P + so);
        // O = P @ V (4 batches, fp16 out)
        {
            dim3 g(DIM / 128, SEQ / 128, HB);
            gemmh_kernel<2, false><<<g, 256, SM_TOTAL, st>>>(
                P + so, Vt + qo, nullptr, O + qo, nullptr, nullptr, nullptr,
                SEQ, DIM,
                (size_t)SEQ * SEQ, (size_t)DIM * SEQ, (size_t)SEQ * DIM);
        }
    }

    // ---- join + out-projection on main stream ----
    cudaEventRecord(e1, s1);
    cudaEventRecord(e2, s2);
    cudaStreamWaitEvent(0, e1, 0);
    cudaStreamWaitEvent(0, e2, 0);
    {
        dim3 g(DIM / 128, MTOT / 128, 1);
        gemmh_kernel<1, false><<<g, 256, SM_TOTAL>>>(
            O, WtH + 3 * wstep, out, nullptr, nullptr, nullptr, bp,
            DIM, DIM, 0, 0, 0);
    }

    // ---- teardown: side streams are joined (out of capture mode);
    // destroying them releases their device memory back to baseline. ----
    cudaEventDestroy(evF);
    cudaEventDestroy(e1);
    cudaEventDestroy(e2);
    cudaStreamDestroy(s1);
    cudaStreamDestroy(s2);
}

// round 13
// speedup vs baseline: 1.1335x; 1.0095x over previous
#include <cuda_runtime.h>
#include <cuda_fp16.h>
#include <stdint.h>
#include <math.h>

#define BATCH 8
#define SEQ   2048
#define DIM   1024
#define MTOT  (BATCH * SEQ)

// ---------------------------------------------------------------------------
// Static device scratch (allocation-free contract).
// ---------------------------------------------------------------------------
__device__ __align__(256) __half g_xH[(size_t)MTOT * DIM];
__device__ __align__(256) __half g_WtH[4][(size_t)DIM * DIM];
__device__ __align__(256) __half g_Q[(size_t)MTOT * DIM];
__device__ __align__(256) __half g_K[(size_t)MTOT * DIM];
__device__ __align__(256) __half g_V[(size_t)MTOT * DIM];
__device__ __align__(256) __half g_Vt[(size_t)MTOT * DIM];
__device__ __align__(256) __half g_O[(size_t)MTOT * DIM];
__device__ __align__(256) float  g_S[(size_t)BATCH * SEQ * SEQ];
__device__ __align__(256) __half g_P[(size_t)BATCH * SEQ * SEQ];

// ---------------------------------------------------------------------------
// Helpers (arch-agnostic PTX only: cp.async / ldmatrix / mma.sync)
// ---------------------------------------------------------------------------
__device__ __forceinline__ uint32_t smem_to_u32(const void* smem_ptr) {
    uint32_t addr;
    asm("{ .reg .u64 tmp; cvta.to.shared.u64 tmp, %1; cvt.u32.u64 %0, tmp; }"
        : "=r"(addr) : "l"(smem_ptr));
    return addr;
}
#define SMEM_SWIZZLE_128B(byte_offset) \
    ((byte_offset) ^ (((byte_offset) >> 3) & 0x70))
#define CP_ASYNC_16(dst_u32, src_ptr) \
    asm volatile("cp.async.cg.shared.global [%0], [%1], 16;" \
                 :: "r"(dst_u32), "l"(src_ptr) : "memory")
#define CP_COMMIT() asm volatile("cp.async.commit_group;" ::: "memory")
#define CP_WAIT(n)  asm volatile("cp.async.wait_group %0;" :: "n"(n) : "memory")

#define LDMATRIX_X4(r0, r1, r2, r3, addr) \
    asm volatile("ldmatrix.sync.aligned.m8n8.x4.shared.b16 {%0,%1,%2,%3}, [%4];" \
                 : "=r"(r0), "=r"(r1), "=r"(r2), "=r"(r3) : "r"(addr))

#define MMA_F16(c, a, b0, b1) \
    asm volatile("mma.sync.aligned.m16n8k16.row.col.f32.f16.f16.f32 " \
                 "{%0,%1,%2,%3}, {%4,%5,%6,%7}, {%8,%9}, {%0,%1,%2,%3};" \
                 : "+f"((c)[0]), "+f"((c)[1]), "+f"((c)[2]), "+f"((c)[3]) \
                 : "r"((a)[0]), "r"((a)[1]), "r"((a)[2]), "r"((a)[3]), \
                   "r"(b0), "r"(b1))

// ---------------------------------------------------------------------------
// GEMM: D[M,N] = A@B^T, single-pass fp16 inputs, fp32 accumulate.
// R8-proven config: tile 128x128, BK=64 (128B rows, SW128), 2-stage cp.async
// double buffer, 8 warps (4m x 2n), warp tile 32x64 m16n8k16, 2 CTAs/SM.
// EPI: 0 = fp32 out, 1 = fp32 + bias, 2 = fp16 out.
// MULTI_B: blockIdx.z selects weight set (B offset) and output (C0/C1/C2).
// ---------------------------------------------------------------------------
#define TILE_BYTES 16384            // 128 rows x 128B
#define STAGE_BYTES (2 * TILE_BYTES)
#define SM_TOTAL (2 * STAGE_BYTES)  // 65536

template <int EPI, bool MULTI_B>
__global__ void __launch_bounds__(256, 2)
gemmh_kernel(const __half* __restrict__ A, const __half* __restrict__ B,
             float* __restrict__ Cf, __half* __restrict__ Ch,
             __half* __restrict__ C1, __half* __restrict__ C2,
             const float* __restrict__ bias,
             int K, int ldC, size_t sA, size_t sB, size_t sC)
{
    extern __shared__ char smem[];
    const uint32_t smem_u = smem_to_u32(smem);
    const int tid = threadIdx.x;
    const int lane = tid & 31;
    const int wid = tid >> 5;
    const int warp_m = wid & 3;
    const int warp_n = wid >> 2;
    const int rowBase = blockIdx.y * 128;
    const int colBase = blockIdx.x * 128;
    const size_t zA = MULTI_B ? 0 : (size_t)blockIdx.z * sA;
    const size_t zB = (size_t)blockIdx.z * sB;
    const size_t zC = MULTI_B ? 0 : (size_t)blockIdx.z * sC;
    __half* ChSel = Ch;
    if (MULTI_B) ChSel = (blockIdx.z == 0) ? Ch : ((blockIdx.z == 1) ? C1 : C2);

    const int ldr_row0 = tid >> 3;
    const int ldr_ch   = tid & 7;

    float acc[2][8][4];
#pragma unroll
    for (int i = 0; i < 2; i++)
#pragma unroll
        for (int j = 0; j < 8; j++)
#pragma unroll
            for (int e = 0; e < 4; e++) acc[i][j][e] = 0.0f;

    const int nIter = K >> 6;

    auto issue_load = [&](int i, int stage) {
        const int kk = i << 6;
        const __half* As = A + zA;
        const __half* Bs = B + zB;
        const uint32_t aBase = smem_u + stage * STAGE_BYTES;
        const uint32_t bBase = aBase + TILE_BYTES;
#pragma unroll
        for (int p = 0; p < 4; p++) {
            const int row = ldr_row0 + p * 32;
            const uint32_t soff = SMEM_SWIZZLE_128B((uint32_t)row * 128 + ldr_ch * 16);
            CP_ASYNC_16(aBase + soff,
                        As + (size_t)(rowBase + row) * K + kk + ldr_ch * 8);
            CP_ASYNC_16(bBase + soff,
                        Bs + (size_t)(colBase + row) * K + kk + ldr_ch * 8);
        }
        CP_COMMIT();
    };

    issue_load(0, 0);

    for (int i = 0; i < nIter; i++) {
        const int stage = i & 1;
        if (i + 1 < nIter) {
            issue_load(i + 1, (i + 1) & 1);
            CP_WAIT(1);
        } else {
            CP_WAIT(0);
        }
        __syncthreads();

        const uint32_t aBase = smem_u + stage * STAGE_BYTES;
        const uint32_t bBase = aBase + TILE_BYTES;
#pragma unroll
        for (int ks = 0; ks < 4; ks++) {
            const uint32_t k2 = ks * 32;
            uint32_t a[2][4];
            uint32_t b[4][4];
#pragma unroll
            for (int fm = 0; fm < 2; fm++) {
                const uint32_t row = warp_m * 32 + fm * 16 + (lane & 15);
                const uint32_t addr = aBase +
                    SMEM_SWIZZLE_128B(row * 128 + k2 + ((lane >> 4) << 4));
                LDMATRIX_X4(a[fm][0], a[fm][1], a[fm][2], a[fm][3], addr);
            }
#pragma unroll
            for (int fn2 = 0; fn2 < 4; fn2++) {
                const uint32_t n = warp_n * 64 + fn2 * 16 + (lane & 7) + ((lane >> 4) << 3);
                const uint32_t addr = bBase +
                    SMEM_SWIZZLE_128B(n * 128 + k2 + (((lane >> 3) & 1) << 4));
                LDMATRIX_X4(b[fn2][0], b[fn2][1], b[fn2][2], b[fn2][3], addr);
            }
#pragma unroll
            for (int fn2 = 0; fn2 < 4; fn2++) {
                MMA_F16(acc[0][fn2 * 2 + 0], a[0], b[fn2][0], b[fn2][1]);
                MMA_F16(acc[0][fn2 * 2 + 1], a[0], b[fn2][2], b[fn2][3]);
                MMA_F16(acc[1][fn2 * 2 + 0], a[1], b[fn2][0], b[fn2][1]);
                MMA_F16(acc[1][fn2 * 2 + 1], a[1], b[fn2][2], b[fn2][3]);
            }
        }
        __syncthreads();
    }

    // Epilogue
    const int gid = lane >> 2;
    const int tig = lane & 3;
#pragma unroll
    for (int fm = 0; fm < 2; fm++) {
#pragma unroll
        for (int fn = 0; fn < 8; fn++) {
            const int r0 = rowBase + warp_m * 32 + fm * 16 + gid;
            const int c  = colBase + warp_n * 64 + fn * 8 + tig * 2;
            const float* ac = acc[fm][fn];
            if (EPI == 2) {
                __half2 h0 = __floats2half2_rn(ac[0], ac[1]);
                __half2 h1 = __floats2half2_rn(ac[2], ac[3]);
                *(uint32_t*)(ChSel + zC + (size_t)r0 * ldC + c)       = *(uint32_t*)&h0;
                *(uint32_t*)(ChSel + zC + (size_t)(r0 + 8) * ldC + c) = *(uint32_t*)&h1;
            } else {
                float2 v0 = make_float2(ac[0], ac[1]);
                float2 v1 = make_float2(ac[2], ac[3]);
                if (EPI == 1) {
                    const float b0 = bias[c], b1 = bias[c + 1];
                    v0.x += b0; v0.y += b1;
                    v1.x += b0; v1.y += b1;
                }
                *(float2*)(Cf + zC + (size_t)r0 * ldC + c)       = v0;
                *(float2*)(Cf + zC + (size_t)(r0 + 8) * ldC + c) = v1;
            }
        }
    }
}

// ---------------------------------------------------------------------------
// fp32 -> fp16 convert (elementwise)
// ---------------------------------------------------------------------------
__global__ void __launch_bounds__(256)
convert_fp16_kernel(const float* __restrict__ x, __half* __restrict__ h)
{
    size_t i = ((size_t)blockIdx.x * 256 + threadIdx.x) * 4;
    float4 v = *(const float4*)(x + i);
    __half2 a = __floats2half2_rn(v.x, v.y);
    __half2 b = __floats2half2_rn(v.z, v.w);
    *(uint2*)(h + i) = make_uint2(*(uint32_t*)&a, *(uint32_t*)&b);
}

// ---------------------------------------------------------------------------
// Transpose + convert ALL FOUR weight matrices in one launch.
// Wq (z==0) pre-scaled by scale*log2e -> S comes out in log2 domain.
// ---------------------------------------------------------------------------
__global__ void __launch_bounds__(256)
transW_all_kernel(const float* __restrict__ W0, const float* __restrict__ W1,
                  const float* __restrict__ W2, const float* __restrict__ W3,
                  __half* __restrict__ thB, float qscale)
{
    const float* W = (blockIdx.z == 0) ? W0 :
                     (blockIdx.z == 1) ? W1 :
                     (blockIdx.z == 2) ? W2 : W3;
    const float sc = (blockIdx.z == 0) ? qscale : 1.0f;
    __half* th = thB + (size_t)blockIdx.z * DIM * DIM;
    __shared__ float t[32][33];
    const int tx = threadIdx.x, ty = threadIdx.y;
    const int x = blockIdx.x * 32 + tx;
    const int y0 = blockIdx.y * 32;
#pragma unroll
    for (int p = 0; p < 4; p++)
        t[ty + 8 * p][tx] = W[(size_t)(y0 + ty + 8 * p) * DIM + x];
    __syncthreads();
    const int ox = blockIdx.y * 32 + tx;
    const int oy0 = blockIdx.x * 32;
#pragma unroll
    for (int p = 0; p < 4; p++)
        th[(size_t)(oy0 + ty + 8 * p) * DIM + ox] =
            __float2half_rn(t[tx][ty + 8 * p] * sc);
}

// ---------------------------------------------------------------------------
// Transpose fp16 per batch: V [SEQ,DIM] -> Vt [DIM,SEQ]
// ---------------------------------------------------------------------------
__global__ void __launch_bounds__(256)
transV_kernel(const __half* __restrict__ iv, __half* __restrict__ ov)
{
    __shared__ __half t0[32][33];
    const size_t zin = (size_t)blockIdx.z * SEQ * DIM;
    const int tx = threadIdx.x, ty = threadIdx.y;
    const int x = blockIdx.x * 32 + tx;
    const int y0 = blockIdx.y * 32;
#pragma unroll
    for (int p = 0; p < 4; p++)
        t0[ty + 8 * p][tx] = iv[zin + (size_t)(y0 + ty + 8 * p) * DIM + x];
    __syncthreads();
    const int ox = blockIdx.y * 32 + tx;
    const int oy0 = blockIdx.x * 32;
#pragma unroll
    for (int p = 0; p < 4; p++)
        ov[zin + (size_t)(oy0 + ty + 8 * p) * SEQ + ox] = t0[tx][ty + 8 * p];
}

// ---------------------------------------------------------------------------
// Row softmax (SEQ=2048 cols); S is ALREADY in log2 domain. Emits fp16 P.
// ---------------------------------------------------------------------------
__global__ void __launch_bounds__(256)
softmax_kernel(const float* __restrict__ S, __half* __restrict__ P)
{
    const size_t row = blockIdx.x;
    const float* p = S + row * SEQ;
    const int tid = threadIdx.x;

    float vals[8];
    float lmax = -INFINITY;
#pragma unroll
    for (int i = 0; i < 8; i++) {
        float v = p[tid + i * 256];
        vals[i] = v;
        lmax = fmaxf(lmax, v);
    }
    __shared__ float red[8];
#pragma unroll
    for (int o = 16; o > 0; o >>= 1)
        lmax = fmaxf(lmax, __shfl_xor_sync(0xffffffffu, lmax, o));
    if ((tid & 31) == 0) red[tid >> 5] = lmax;
    __syncthreads();
    float m = red[0];
#pragma unroll
    for (int w = 1; w < 8; w++) m = fmaxf(m, red[w]);
    __syncthreads();

    float lsum = 0.0f;
#pragma unroll
    for (int i = 0; i < 8; i++) {
        vals[i] = exp2f(vals[i] - m);
        lsum += vals[i];
    }
#pragma unroll
    for (int o = 16; o > 0; o >>= 1)
        lsum += __shfl_xor_sync(0xffffffffu, lsum, o);
    if ((tid & 31) == 0) red[tid >> 5] = lsum;
    __syncthreads();
    float tot = 0.0f;
#pragma unroll
    for (int w = 0; w < 8; w++) tot += red[w];
    const float rinv = 1.0f / tot;

#pragma unroll
    for (int i = 0; i < 8; i++)
        P[row * SEQ + tid + i * 256] = __float2half_rn(vals[i] * rinv);
}

// ---------------------------------------------------------------------------
// kernel_launch — maximal fork schedule:
//   fork0:  s1: transW        | s2: convert x
//   join -> main: QKV GEMM (needs both)
//   fork1:  s1: transV(all) -> evT, S(0), softmax(0), PV(0), outproj(0)
//           s2: S(1), softmax(1), [wait evT] PV(1), outproj(1)
//   join -> end.
// Memory kernels (transV/softmax/convert) hide under the other stream's
// tensor kernels; out-projection halves overlap the opposite PV tail.
// Streams/events created AND destroyed per call; both streams are joined
// back into the origin stream before destruction (capture-legal, memory
// returns to baseline for the harness checkpoint).
// ---------------------------------------------------------------------------
extern "C" void kernel_launch(void* const* d_in, const int* in_sizes, int n_in,
                              void* d_out, int out_size)
{
    (void)in_sizes; (void)n_in; (void)out_size;
    const float* x  = (const float*)d_in[0];
    const float* Wq = (const float*)d_in[1];
    const float* Wk = (const float*)d_in[2];
    const float* Wv = (const float*)d_in[3];
    const float* Wp = (const float*)d_in[4];
    const float* bp = (const float*)d_in[5];
    float* out = (float*)d_out;

    __half *xH, *WtH, *Q, *K, *V, *Vt, *O, *P;
    float* S;
    cudaGetSymbolAddress((void**)&xH, g_xH);
    cudaGetSymbolAddress((void**)&WtH, g_WtH);
    cudaGetSymbolAddress((void**)&Q, g_Q);
    cudaGetSymbolAddress((void**)&K, g_K);
    cudaGetSymbolAddress((void**)&V, g_V);
    cudaGetSymbolAddress((void**)&Vt, g_Vt);
    cudaGetSymbolAddress((void**)&O, g_O);
    cudaGetSymbolAddress((void**)&S, g_S);
    cudaGetSymbolAddress((void**)&P, g_P);

    const size_t wstep = (size_t)DIM * DIM;

    cudaFuncSetAttribute(gemmh_kernel<0, false>, cudaFuncAttributeMaxDynamicSharedMemorySize, SM_TOTAL);
    cudaFuncSetAttribute(gemmh_kernel<1, false>, cudaFuncAttributeMaxDynamicSharedMemorySize, SM_TOTAL);
    cudaFuncSetAttribute(gemmh_kernel<2, false>, cudaFuncAttributeMaxDynamicSharedMemorySize, SM_TOTAL);
    cudaFuncSetAttribute(gemmh_kernel<2, true>,  cudaFuncAttributeMaxDynamicSharedMemorySize, SM_TOTAL);

    // Fork plumbing — created per call, destroyed at the end of this call.
    cudaStream_t s1, s2;
    cudaEvent_t evF, eP1, eP2, evQ, evT, eJ1, eJ2;
    cudaStreamCreateWithFlags(&s1, cudaStreamNonBlocking);
    cudaStreamCreateWithFlags(&s2, cudaStreamNonBlocking);
    cudaEventCreateWithFlags(&evF, cudaEventDisableTiming);
    cudaEventCreateWithFlags(&eP1, cudaEventDisableTiming);
    cudaEventCreateWithFlags(&eP2, cudaEventDisableTiming);
    cudaEventCreateWithFlags(&evQ, cudaEventDisableTiming);
    cudaEventCreateWithFlags(&evT, cudaEventDisableTiming);
    cudaEventCreateWithFlags(&eJ1, cudaEventDisableTiming);
    cudaEventCreateWithFlags(&eJ2, cudaEventDisableTiming);

    const size_t HB = 4;                       // batches per half
    const size_t qkvOff = HB * SEQ * DIM;      // elements per half (Q/K/V/O/out rows)
    const size_t sOff   = HB * SEQ * SEQ;      // S/P elements per half

    // ---- fork 0: prep ----
    cudaEventRecord(evF, 0);
    cudaStreamWaitEvent(s1, evF, 0);
    cudaStreamWaitEvent(s2, evF, 0);
    {
        dim3 g(DIM / 32, DIM / 32, 4), b(32, 8);
        transW_all_kernel<<<g, b, 0, s1>>>(Wq, Wk, Wv, Wp, WtH,
                                           0.03125f * 1.4426950408889634f);
    }
    convert_fp16_kernel<<<(size_t)MTOT * DIM / 1024, 256, 0, s2>>>(x, xH);
    cudaEventRecord(eP1, s1);
    cudaEventRecord(eP2, s2);

    // ---- main: QKV GEMM (needs transW + convert) ----
    cudaStreamWaitEvent(0, eP1, 0);
    cudaStreamWaitEvent(0, eP2, 0);
    {
        dim3 g(DIM / 128, MTOT / 128, 3);
        gemmh_kernel<2, true><<<g, 256, SM_TOTAL>>>(
            xH, WtH, nullptr, Q, K, V, nullptr,
            DIM, DIM, 0, wstep, 0);
    }
    cudaEventRecord(evQ, 0);
    cudaStreamWaitEvent(s1, evQ, 0);
    cudaStreamWaitEvent(s2, evQ, 0);

    // ---- fork 1: attention + out-projection, split by batch halves ----
    // s1: transV(all 8 batches, memory) overlaps s2's S(1) (tensor)
    {
        dim3 g(DIM / 32, SEQ / 32, BATCH), b(32, 8);
        transV_kernel<<<g, b, 0, s1>>>(V, Vt);
    }
    cudaEventRecord(evT, s1);

    // s1: half 0 chain
    {
        dim3 g(SEQ / 128, SEQ / 128, HB);
        gemmh_kernel<0, false><<<g, 256, SM_TOTAL, s1>>>(
            Q, K, S, nullptr, nullptr, nullptr, nullptr,
            DIM, SEQ,
            (size_t)SEQ * DIM, (size_t)SEQ * DIM, (size_t)SEQ * SEQ);
    }
    softmax_kernel<<<HB * SEQ, 256, 0, s1>>>(S, P);
    {
        dim3 g(DIM / 128, SEQ / 128, HB);
        gemmh_kernel<2, false><<<g, 256, SM_TOTAL, s1>>>(
            P, Vt, nullptr, O, nullptr, nullptr, nullptr,
            SEQ, DIM,
            (size_t)SEQ * SEQ, (size_t)DIM * SEQ, (size_t)SEQ * DIM);
    }
    {
        dim3 g(DIM / 128, (HB * SEQ) / 128, 1);
        gemmh_kernel<1, false><<<g, 256, SM_TOTAL, s1>>>(
            O, WtH + 3 * wstep, out, nullptr, nullptr, nullptr, bp,
            DIM, DIM, 0, 0, 0);
    }
    cudaEventRecord(eJ1, s1);

    // s2: half 1 chain (PV waits on transV via evT)
    {
        dim3 g(SEQ / 128, SEQ / 128, HB);
        gemmh_kernel<0, false><<<g, 256, SM_TOTAL, s2>>>(
            Q + qkvOff, K + qkvOff, S + sOff, nullptr, nullptr, nullptr, nullptr,
            DIM, SEQ,
            (size_t)SEQ * DIM, (size_t)SEQ * DIM, (size_t)SEQ * SEQ);
    }
    softmax_kernel<<<HB * SEQ, 256, 0, s2>>>(S + sOff, P + sOff);
    cudaStreamWaitEvent(s2, evT, 0);
    {
        dim3 g(DIM / 128, SEQ / 128, HB);
        gemmh_kernel<2, false><<<g, 256, SM_TOTAL, s2>>>(
            P + sOff, Vt + qkvOff, nullptr, O + qkvOff, nullptr, nullptr, nullptr,
            SEQ, DIM,
            (size_t)SEQ * SEQ, (size_t)DIM * SEQ, (size_t)SEQ * DIM);
    }
    {
        dim3 g(DIM / 128, (HB * SEQ) / 128, 1);
        gemmh_kernel<1, false><<<g, 256, SM_TOTAL, s2>>>(
            O + qkvOff, WtH + 3 * wstep, out + qkvOff, nullptr, nullptr, nullptr, bp,
            DIM, DIM, 0, 0, 0);
    }
    cudaEventRecord(eJ2, s2);

    // ---- join back into origin stream ----
    cudaStreamWaitEvent(0, eJ1, 0);
    cudaStreamWaitEvent(0, eJ2, 0);

    // ---- teardown (streams joined -> out of capture; memory to baseline) ----
    cudaEventDestroy(evF);
    cudaEventDestroy(eP1);
    cudaEventDestroy(eP2);
    cudaEventDestroy(evQ);
    cudaEventDestroy(evT);
    cudaEventDestroy(eJ1);
    cudaEventDestroy(eJ2);
    cudaStreamDestroy(s1);
    cudaStreamDestroy(s2);
}

// round 14
// speedup vs baseline: 1.1575x; 1.0211x over previous
#include <cuda_runtime.h>
#include <cuda_fp16.h>
#include <stdint.h>
#include <math.h>

#define BATCH 8
#define SEQ   2048
#define DIM   1024
#define MTOT  (BATCH * SEQ)

// ---------------------------------------------------------------------------
// Static device scratch (allocation-free contract). V is never materialized:
// the QKV GEMM's z==2 epilogue writes Vt (per-batch [DIM, SEQ]) directly.
// ---------------------------------------------------------------------------
__device__ __align__(256) __half g_xH[(size_t)MTOT * DIM];
__device__ __align__(256) __half g_WtH[4][(size_t)DIM * DIM];
__device__ __align__(256) __half g_Q[(size_t)MTOT * DIM];
__device__ __align__(256) __half g_K[(size_t)MTOT * DIM];
__device__ __align__(256) __half g_Vt[(size_t)MTOT * DIM];
__device__ __align__(256) __half g_O[(size_t)MTOT * DIM];
__device__ __align__(256) float  g_S[(size_t)BATCH * SEQ * SEQ];
__device__ __align__(256) __half g_P[(size_t)BATCH * SEQ * SEQ];

// ---------------------------------------------------------------------------
// Helpers (arch-agnostic PTX only: cp.async / ldmatrix / mma.sync)
// ---------------------------------------------------------------------------
__device__ __forceinline__ uint32_t smem_to_u32(const void* smem_ptr) {
    uint32_t addr;
    asm("{ .reg .u64 tmp; cvta.to.shared.u64 tmp, %1; cvt.u32.u64 %0, tmp; }"
        : "=r"(addr) : "l"(smem_ptr));
    return addr;
}
#define SMEM_SWIZZLE_128B(byte_offset) \
    ((byte_offset) ^ (((byte_offset) >> 3) & 0x70))
#define CP_ASYNC_16(dst_u32, src_ptr) \
    asm volatile("cp.async.cg.shared.global [%0], [%1], 16;" \
                 :: "r"(dst_u32), "l"(src_ptr) : "memory")
#define CP_COMMIT() asm volatile("cp.async.commit_group;" ::: "memory")
#define CP_WAIT(n)  asm volatile("cp.async.wait_group %0;" :: "n"(n) : "memory")

#define LDMATRIX_X4(r0, r1, r2, r3, addr) \
    asm volatile("ldmatrix.sync.aligned.m8n8.x4.shared.b16 {%0,%1,%2,%3}, [%4];" \
                 : "=r"(r0), "=r"(r1), "=r"(r2), "=r"(r3) : "r"(addr))

#define MMA_F16(c, a, b0, b1) \
    asm volatile("mma.sync.aligned.m16n8k16.row.col.f32.f16.f16.f32 " \
                 "{%0,%1,%2,%3}, {%4,%5,%6,%7}, {%8,%9}, {%0,%1,%2,%3};" \
                 : "+f"((c)[0]), "+f"((c)[1]), "+f"((c)[2]), "+f"((c)[3]) \
                 : "r"((a)[0]), "r"((a)[1]), "r"((a)[2]), "r"((a)[3]), \
                   "r"(b0), "r"(b1))

// ---------------------------------------------------------------------------
// GEMM: D[M,N] = A@B^T, single-pass fp16 inputs, fp32 accumulate.
// R8-proven config: tile 128x128, BK=64 (128B rows, SW128), 2-stage cp.async
// double buffer, 8 warps (4m x 2n), warp tile 32x64 m16n8k16, 2 CTAs/SM.
// EPI: 0 = fp32 out, 1 = fp32 + bias, 2 = fp16 out.
// MULTI_B: blockIdx.z selects weight set; z==0 -> Ch (Q), z==1 -> C1 (K),
//          z==2 -> TRANSPOSED fp16 write into C2 as per-batch Vt[DIM,SEQ]
//          (tile staged in smem [128][130] for conflict-free transpose).
// rowOff: global row offset of this launch's tile grid (batch-half splits).
// ---------------------------------------------------------------------------
#define TILE_BYTES 16384            // 128 rows x 128B
#define STAGE_BYTES (2 * TILE_BYTES)
#define SM_TOTAL (2 * STAGE_BYTES)  // 65536

template <int EPI, bool MULTI_B>
__global__ void __launch_bounds__(256, 2)
gemmh_kernel(const __half* __restrict__ A, const __half* __restrict__ B,
             float* __restrict__ Cf, __half* __restrict__ Ch,
             __half* __restrict__ C1, __half* __restrict__ C2,
             const float* __restrict__ bias,
             int K, int ldC, size_t sA, size_t sB, size_t sC, int rowOff)
{
    extern __shared__ char smem[];
    const uint32_t smem_u = smem_to_u32(smem);
    const int tid = threadIdx.x;
    const int lane = tid & 31;
    const int wid = tid >> 5;
    const int warp_m = wid & 3;
    const int warp_n = wid >> 2;
    const int rowBase = rowOff + blockIdx.y * 128;
    const int colBase = blockIdx.x * 128;
    const size_t zA = MULTI_B ? 0 : (size_t)blockIdx.z * sA;
    const size_t zB = (size_t)blockIdx.z * sB;
    const size_t zC = MULTI_B ? 0 : (size_t)blockIdx.z * sC;
    __half* ChSel = Ch;
    if (MULTI_B) ChSel = (blockIdx.z == 0) ? Ch : ((blockIdx.z == 1) ? C1 : C2);

    const int ldr_row0 = tid >> 3;
    const int ldr_ch   = tid & 7;

    float acc[2][8][4];
#pragma unroll
    for (int i = 0; i < 2; i++)
#pragma unroll
        for (int j = 0; j < 8; j++)
#pragma unroll
            for (int e = 0; e < 4; e++) acc[i][j][e] = 0.0f;

    const int nIter = K >> 6;

    auto issue_load = [&](int i, int stage) {
        const int kk = i << 6;
        const __half* As = A + zA;
        const __half* Bs = B + zB;
        const uint32_t aBase = smem_u + stage * STAGE_BYTES;
        const uint32_t bBase = aBase + TILE_BYTES;
#pragma unroll
        for (int p = 0; p < 4; p++) {
            const int row = ldr_row0 + p * 32;
            const uint32_t soff = SMEM_SWIZZLE_128B((uint32_t)row * 128 + ldr_ch * 16);
            CP_ASYNC_16(aBase + soff,
                        As + (size_t)(rowBase + row) * K + kk + ldr_ch * 8);
            CP_ASYNC_16(bBase + soff,
                        Bs + (size_t)(colBase + row) * K + kk + ldr_ch * 8);
        }
        CP_COMMIT();
    };

    issue_load(0, 0);

    for (int i = 0; i < nIter; i++) {
        const int stage = i & 1;
        if (i + 1 < nIter) {
            issue_load(i + 1, (i + 1) & 1);
            CP_WAIT(1);
        } else {
            CP_WAIT(0);
        }
        __syncthreads();

        const uint32_t aBase = smem_u + stage * STAGE_BYTES;
        const uint32_t bBase = aBase + TILE_BYTES;
#pragma unroll
        for (int ks = 0; ks < 4; ks++) {
            const uint32_t k2 = ks * 32;
            uint32_t a[2][4];
            uint32_t b[4][4];
#pragma unroll
            for (int fm = 0; fm < 2; fm++) {
                const uint32_t row = warp_m * 32 + fm * 16 + (lane & 15);
                const uint32_t addr = aBase +
                    SMEM_SWIZZLE_128B(row * 128 + k2 + ((lane >> 4) << 4));
                LDMATRIX_X4(a[fm][0], a[fm][1], a[fm][2], a[fm][3], addr);
            }
#pragma unroll
            for (int fn2 = 0; fn2 < 4; fn2++) {
                const uint32_t n = warp_n * 64 + fn2 * 16 + (lane & 7) + ((lane >> 4) << 3);
                const uint32_t addr = bBase +
                    SMEM_SWIZZLE_128B(n * 128 + k2 + (((lane >> 3) & 1) << 4));
                LDMATRIX_X4(b[fn2][0], b[fn2][1], b[fn2][2], b[fn2][3], addr);
            }
#pragma unroll
            for (int fn2 = 0; fn2 < 4; fn2++) {
                MMA_F16(acc[0][fn2 * 2 + 0], a[0], b[fn2][0], b[fn2][1]);
                MMA_F16(acc[0][fn2 * 2 + 1], a[0], b[fn2][2], b[fn2][3]);
                MMA_F16(acc[1][fn2 * 2 + 0], a[1], b[fn2][0], b[fn2][1]);
                MMA_F16(acc[1][fn2 * 2 + 1], a[1], b[fn2][2], b[fn2][3]);
            }
        }
        __syncthreads();
    }

    // Epilogue
    const int gid = lane >> 2;
    const int tig = lane & 3;

    if (EPI == 2 && MULTI_B && blockIdx.z == 2) {
        // ---- transposed V output: stage tile in smem, write Vt[d, t] ----
        __half* tsm = reinterpret_cast<__half*>(smem);   // [128][130] fp16
#pragma unroll
        for (int fm = 0; fm < 2; fm++) {
#pragma unroll
            for (int fn = 0; fn < 8; fn++) {
                const int r = warp_m * 32 + fm * 16 + gid;     // tile-local t
                const int c = warp_n * 64 + fn * 8 + tig * 2;  // tile-local d
                const float* ac = acc[fm][fn];
                __half2 h0 = __floats2half2_rn(ac[0], ac[1]);
                __half2 h1 = __floats2half2_rn(ac[2], ac[3]);
                *(__half2*)(&tsm[(size_t)r * 130 + c])       = h0;
                *(__half2*)(&tsm[(size_t)(r + 8) * 130 + c]) = h1;
            }
        }
        __syncthreads();
        const int gRow0 = rowBase;                    // 128-aligned, within one batch
        const size_t bidx = (size_t)gRow0 / SEQ;
        const int tl0 = gRow0 % SEQ;
        __half* dstBase = C2 + bidx * (size_t)DIM * SEQ + tl0;
#pragma unroll 1
        for (int ccb = 0; ccb < 16; ccb++) {
            const int cc = wid * 16 + ccb;            // tile-local d
            __half* drow = dstBase + (size_t)(colBase + cc) * SEQ;
#pragma unroll
            for (int j = 0; j < 4; j++) {
                const int t = lane + 32 * j;
                drow[t] = tsm[(size_t)t * 130 + cc];
            }
        }
        return;
    }

#pragma unroll
    for (int fm = 0; fm < 2; fm++) {
#pragma unroll
        for (int fn = 0; fn < 8; fn++) {
            const int r0 = rowBase + warp_m * 32 + fm * 16 + gid;
            const int c  = colBase + warp_n * 64 + fn * 8 + tig * 2;
            const float* ac = acc[fm][fn];
            if (EPI == 2) {
                __half2 h0 = __floats2half2_rn(ac[0], ac[1]);
                __half2 h1 = __floats2half2_rn(ac[2], ac[3]);
                *(uint32_t*)(ChSel + zC + (size_t)r0 * ldC + c)       = *(uint32_t*)&h0;
                *(uint32_t*)(ChSel + zC + (size_t)(r0 + 8) * ldC + c) = *(uint32_t*)&h1;
            } else {
                float2 v0 = make_float2(ac[0], ac[1]);
                float2 v1 = make_float2(ac[2], ac[3]);
                if (EPI == 1) {
                    const float b0 = bias[c], b1 = bias[c + 1];
                    v0.x += b0; v0.y += b1;
                    v1.x += b0; v1.y += b1;
                }
                *(float2*)(Cf + zC + (size_t)r0 * ldC + c)       = v0;
                *(float2*)(Cf + zC + (size_t)(r0 + 8) * ldC + c) = v1;
            }
        }
    }
}

// ---------------------------------------------------------------------------
// fp32 -> fp16 convert (elementwise)
// ---------------------------------------------------------------------------
__global__ void __launch_bounds__(256)
convert_fp16_kernel(const float* __restrict__ x, __half* __restrict__ h)
{
    size_t i = ((size_t)blockIdx.x * 256 + threadIdx.x) * 4;
    float4 v = *(const float4*)(x + i);
    __half2 a = __floats2half2_rn(v.x, v.y);
    __half2 b = __floats2half2_rn(v.z, v.w);
    *(uint2*)(h + i) = make_uint2(*(uint32_t*)&a, *(uint32_t*)&b);
}

// ---------------------------------------------------------------------------
// Transpose + convert ALL FOUR weight matrices in one launch.
// Wq (z==0) pre-scaled by scale*log2e -> S comes out in log2 domain.
// ---------------------------------------------------------------------------
__global__ void __launch_bounds__(256)
transW_all_kernel(const float* __restrict__ W0, const float* __restrict__ W1,
                  const float* __restrict__ W2, const float* __restrict__ W3,
                  __half* __restrict__ thB, float qscale)
{
    const float* W = (blockIdx.z == 0) ? W0 :
                     (blockIdx.z == 1) ? W1 :
                     (blockIdx.z == 2) ? W2 : W3;
    const float sc = (blockIdx.z == 0) ? qscale : 1.0f;
    __half* th = thB + (size_t)blockIdx.z * DIM * DIM;
    __shared__ float t[32][33];
    const int tx = threadIdx.x, ty = threadIdx.y;
    const int x = blockIdx.x * 32 + tx;
    const int y0 = blockIdx.y * 32;
#pragma unroll
    for (int p = 0; p < 4; p++)
        t[ty + 8 * p][tx] = W[(size_t)(y0 + ty + 8 * p) * DIM + x];
    __syncthreads();
    const int ox = blockIdx.y * 32 + tx;
    const int oy0 = blockIdx.x * 32;
#pragma unroll
    for (int p = 0; p < 4; p++)
        th[(size_t)(oy0 + ty + 8 * p) * DIM + ox] =
            __float2half_rn(t[tx][ty + 8 * p] * sc);
}

// ---------------------------------------------------------------------------
// Row softmax (SEQ=2048 cols); S is ALREADY in log2 domain. Emits fp16 P.
// ---------------------------------------------------------------------------
__global__ void __launch_bounds__(256)
softmax_kernel(const float* __restrict__ S, __half* __restrict__ P)
{
    const size_t row = blockIdx.x;
    const float* p = S + row * SEQ;
    const int tid = threadIdx.x;

    float vals[8];
    float lmax = -INFINITY;
#pragma unroll
    for (int i = 0; i < 8; i++) {
        float v = p[tid + i * 256];
        vals[i] = v;
        lmax = fmaxf(lmax, v);
    }
    __shared__ float red[8];
#pragma unroll
    for (int o = 16; o > 0; o >>= 1)
        lmax = fmaxf(lmax, __shfl_xor_sync(0xffffffffu, lmax, o));
    if ((tid & 31) == 0) red[tid >> 5] = lmax;
    __syncthreads();
    float m = red[0];
#pragma unroll
    for (int w = 1; w < 8; w++) m = fmaxf(m, red[w]);
    __syncthreads();

    float lsum = 0.0f;
#pragma unroll
    for (int i = 0; i < 8; i++) {
        vals[i] = exp2f(vals[i] - m);
        lsum += vals[i];
    }
#pragma unroll
    for (int o = 16; o > 0; o >>= 1)
        lsum += __shfl_xor_sync(0xffffffffu, lsum, o);
    if ((tid & 31) == 0) red[tid >> 5] = lsum;
    __syncthreads();
    float tot = 0.0f;
#pragma unroll
    for (int w = 0; w < 8; w++) tot += red[w];
    const float rinv = 1.0f / tot;

#pragma unroll
    for (int i = 0; i < 8; i++)
        P[row * SEQ + tid + i * 256] = __float2half_rn(vals[i] * rinv);
}

// ---------------------------------------------------------------------------
// kernel_launch — fully half-symmetric pipelined schedule:
//   fork0:  s1: transW -> eW     | s2: convert(h0) -> eC0, convert(h1) -> eC1
//   main:   [eW,eC0] QKV(h0) -> evQ0 ; [eC1] QKV(h1) -> evQ1
//           (QKV z==2 epilogue writes Vt directly; no transV kernel)
//   s1: [evQ0] S(0) -> softmax(0) -> PV(0) -> outproj(0) -> eJ1
//   s2: [evQ1] S(1) -> softmax(1) -> PV(1) -> outproj(1) -> eJ2
//   main: [eJ1,eJ2] done.
// Streams/events created AND destroyed per call; both streams joined back
// into the origin stream before destruction (capture-legal, memory baseline).
// ---------------------------------------------------------------------------
extern "C" void kernel_launch(void* const* d_in, const int* in_sizes, int n_in,
                              void* d_out, int out_size)
{
    (void)in_sizes; (void)n_in; (void)out_size;
    const float* x  = (const float*)d_in[0];
    const float* Wq = (const float*)d_in[1];
    const float* Wk = (const float*)d_in[2];
    const float* Wv = (const float*)d_in[3];
    const float* Wp = (const float*)d_in[4];
    const float* bp = (const float*)d_in[5];
    float* out = (float*)d_out;

    __half *xH, *WtH, *Q, *K, *Vt, *O, *P;
    float* S;
    cudaGetSymbolAddress((void**)&xH, g_xH);
    cudaGetSymbolAddress((void**)&WtH, g_WtH);
    cudaGetSymbolAddress((void**)&Q, g_Q);
    cudaGetSymbolAddress((void**)&K, g_K);
    cudaGetSymbolAddress((void**)&Vt, g_Vt);
    cudaGetSymbolAddress((void**)&O, g_O);
    cudaGetSymbolAddress((void**)&S, g_S);
    cudaGetSymbolAddress((void**)&P, g_P);

    const size_t wstep = (size_t)DIM * DIM;

    cudaFuncSetAttribute(gemmh_kernel<0, false>, cudaFuncAttributeMaxDynamicSharedMemorySize, SM_TOTAL);
    cudaFuncSetAttribute(gemmh_kernel<1, false>, cudaFuncAttributeMaxDynamicSharedMemorySize, SM_TOTAL);
    cudaFuncSetAttribute(gemmh_kernel<2, false>, cudaFuncAttributeMaxDynamicSharedMemorySize, SM_TOTAL);
    cudaFuncSetAttribute(gemmh_kernel<2, true>,  cudaFuncAttributeMaxDynamicSharedMemorySize, SM_TOTAL);

    // Fork plumbing — created per call, destroyed at the end of this call.
    cudaStream_t s1, s2;
    cudaEvent_t evF, eW, eC0, eC1, evQ0, evQ1, eJ1, eJ2;
    cudaStreamCreateWithFlags(&s1, cudaStreamNonBlocking);
    cudaStreamCreateWithFlags(&s2, cudaStreamNonBlocking);
    cudaEventCreateWithFlags(&evF, cudaEventDisableTiming);
    cudaEventCreateWithFlags(&eW,  cudaEventDisableTiming);
    cudaEventCreateWithFlags(&eC0, cudaEventDisableTiming);
    cudaEventCreateWithFlags(&eC1, cudaEventDisableTiming);
    cudaEventCreateWithFlags(&evQ0, cudaEventDisableTiming);
    cudaEventCreateWithFlags(&evQ1, cudaEventDisableTiming);
    cudaEventCreateWithFlags(&eJ1, cudaEventDisableTiming);
    cudaEventCreateWithFlags(&eJ2, cudaEventDisableTiming);

    const size_t HB = 4;                       // batches per half
    const size_t HROWS = HB * SEQ;             // rows per half (8192)
    const size_t qkvOff = HROWS * DIM;         // fp16 elements per half
    const size_t sOff   = HB * SEQ * SEQ;      // S/P elements per half

    // ---- fork 0: prep ----
    cudaEventRecord(evF, 0);
    cudaStreamWaitEvent(s1, evF, 0);
    cudaStreamWaitEvent(s2, evF, 0);
    {
        dim3 g(DIM / 32, DIM / 32, 4), b(32, 8);
        transW_all_kernel<<<g, b, 0, s1>>>(Wq, Wk, Wv, Wp, WtH,
                                           0.03125f * 1.4426950408889634f);
    }
    cudaEventRecord(eW, s1);
    convert_fp16_kernel<<<qkvOff / 1024, 256, 0, s2>>>(x, xH);
    cudaEventRecord(eC0, s2);
    convert_fp16_kernel<<<qkvOff / 1024, 256, 0, s2>>>(x + qkvOff, xH + qkvOff);
    cudaEventRecord(eC1, s2);

    // ---- main: QKV by halves (z==2 writes Vt transposed in-epilogue) ----
    cudaStreamWaitEvent(0, eW, 0);
    cudaStreamWaitEvent(0, eC0, 0);
    {
        dim3 g(DIM / 128, HROWS / 128, 3);
        gemmh_kernel<2, true><<<g, 256, SM_TOTAL>>>(
            xH, WtH, nullptr, Q, K, Vt, nullptr,
            DIM, DIM, 0, wstep, 0, 0);
    }
    cudaEventRecord(evQ0, 0);
    cudaStreamWaitEvent(0, eC1, 0);
    {
        dim3 g(DIM / 128, HROWS / 128, 3);
        gemmh_kernel<2, true><<<g, 256, SM_TOTAL>>>(
            xH, WtH, nullptr, Q, K, Vt, nullptr,
            DIM, DIM, 0, wstep, 0, (int)HROWS);
    }
    cudaEventRecord(evQ1, 0);

    // ---- attention half-chains (no cross-half dependencies) ----
    for (int h = 0; h < 2; h++) {
        cudaStream_t st = h ? s2 : s1;
        cudaStreamWaitEvent(st, h ? evQ1 : evQ0, 0);
        const size_t qo = h * qkvOff;
        const size_t so = h * sOff;

        {   // S = Q @ K^T (4 batches, fp32 log2-domain logits)
            dim3 g(SEQ / 128, SEQ / 128, HB);
            gemmh_kernel<0, false><<<g, 256, SM_TOTAL, st>>>(
                Q + qo, K + qo, S + so, nullptr, nullptr, nullptr, nullptr,
                DIM, SEQ,
                (size_t)SEQ * DIM, (size_t)SEQ * DIM, (size_t)SEQ * SEQ, 0);
        }
        softmax_kernel<<<HB * SEQ, 256, 0, st>>>(S + so, P + so);
        {   // O = P @ V (B = Vt, per-batch [DIM, SEQ])
            dim3 g(DIM / 128, SEQ / 128, HB);
            gemmh_kernel<2, false><<<g, 256, SM_TOTAL, st>>>(
                P + so, Vt + qo, nullptr, O + qo, nullptr, nullptr, nullptr,
                SEQ, DIM,
                (size_t)SEQ * SEQ, (size_t)DIM * SEQ, (size_t)SEQ * DIM, 0);
        }
        {   // out = O @ Wp^T + bp (this half's rows)
            dim3 g(DIM / 128, HROWS / 128, 1);
            gemmh_kernel<1, false><<<g, 256, SM_TOTAL, st>>>(
                O + qo, WtH + 3 * wstep, out + qo, nullptr, nullptr, nullptr, bp,
                DIM, DIM, 0, 0, 0, 0);
        }
        cudaEventRecord(h ? eJ2 : eJ1, st);
    }

    // ---- join back into origin stream ----
    cudaStreamWaitEvent(0, eJ1, 0);
    cudaStreamWaitEvent(0, eJ2, 0);

    // ---- teardown (streams joined -> out of capture; memory to baseline) ----
    cudaEventDestroy(evF);
    cudaEventDestroy(eW);
    cudaEventDestroy(eC0);
    cudaEventDestroy(eC1);
    cudaEventDestroy(evQ0);
    cudaEventDestroy(evQ1);
    cudaEventDestroy(eJ1);
    cudaEventDestroy(eJ2);
    cudaStreamDestroy(s1);
    cudaStreamDestroy(s2);
}

// round 15
// speedup vs baseline: 1.1937x; 1.0313x over previous
#include <cuda_runtime.h>
#include <cuda_fp16.h>
#include <stdint.h>
#include <math.h>

#define BATCH 8
#define SEQ   2048
#define DIM   1024
#define MTOT  (BATCH * SEQ)

// ---------------------------------------------------------------------------
// Static device scratch (allocation-free contract). V is never materialized
// (QKV z==2 epilogue writes Vt). S is never materialized in fp32: the S GEMM
// epilogue applies exp2 and writes unnormalized E (fp16); normalization is
// folded into the PV epilogue via per-row 1/sum.
// ---------------------------------------------------------------------------
__device__ __align__(256) __half g_xH[(size_t)MTOT * DIM];
__device__ __align__(256) __half g_WtH[4][(size_t)DIM * DIM];
__device__ __align__(256) __half g_Q[(size_t)MTOT * DIM];
__device__ __align__(256) __half g_K[(size_t)MTOT * DIM];
__device__ __align__(256) __half g_Vt[(size_t)MTOT * DIM];
__device__ __align__(256) __half g_O[(size_t)MTOT * DIM];
__device__ __align__(256) __half g_E[(size_t)BATCH * SEQ * SEQ];
__device__ __align__(256) float  g_Rinv[(size_t)MTOT];

// ---------------------------------------------------------------------------
// Helpers (arch-agnostic PTX only: cp.async / ldmatrix / mma.sync)
// ---------------------------------------------------------------------------
__device__ __forceinline__ uint32_t smem_to_u32(const void* smem_ptr) {
    uint32_t addr;
    asm("{ .reg .u64 tmp; cvta.to.shared.u64 tmp, %1; cvt.u32.u64 %0, tmp; }"
        : "=r"(addr) : "l"(smem_ptr));
    return addr;
}
#define SMEM_SWIZZLE_128B(byte_offset) \
    ((byte_offset) ^ (((byte_offset) >> 3) & 0x70))
#define CP_ASYNC_16(dst_u32, src_ptr) \
    asm volatile("cp.async.cg.shared.global [%0], [%1], 16;" \
                 :: "r"(dst_u32), "l"(src_ptr) : "memory")
#define CP_COMMIT() asm volatile("cp.async.commit_group;" ::: "memory")
#define CP_WAIT(n)  asm volatile("cp.async.wait_group %0;" :: "n"(n) : "memory")

#define LDMATRIX_X4(r0, r1, r2, r3, addr) \
    asm volatile("ldmatrix.sync.aligned.m8n8.x4.shared.b16 {%0,%1,%2,%3}, [%4];" \
                 : "=r"(r0), "=r"(r1), "=r"(r2), "=r"(r3) : "r"(addr))

#define MMA_F16(c, a, b0, b1) \
    asm volatile("mma.sync.aligned.m16n8k16.row.col.f32.f16.f16.f32 " \
                 "{%0,%1,%2,%3}, {%4,%5,%6,%7}, {%8,%9}, {%0,%1,%2,%3};" \
                 : "+f"((c)[0]), "+f"((c)[1]), "+f"((c)[2]), "+f"((c)[3]) \
                 : "r"((a)[0]), "r"((a)[1]), "r"((a)[2]), "r"((a)[3]), \
                   "r"(b0), "r"(b1))

// ---------------------------------------------------------------------------
// GEMM: D[M,N] = A@B^T, single-pass fp16 inputs, fp32 accumulate.
// R8-proven config: tile 128x128, BK=64 (128B rows, SW128), 2-stage cp.async
// double buffer, 8 warps (4m x 2n), warp tile 32x64 m16n8k16, 2 CTAs/SM.
// EPI: 0 = fp32 out, 1 = fp32 + bias, 2 = fp16 out,
//      3 = fp16 exp2(acc) out (unnormalized attention weights E),
//      4 = fp16 acc * rinv[row] out (normalized PV; bias ptr = rinv floats,
//          indexed blockIdx.z * SEQ + row).
// MULTI_B: blockIdx.z selects weight set; z==0 -> Ch (Q), z==1 -> C1 (K),
//          z==2 -> TRANSPOSED fp16 write into C2 as per-batch Vt[DIM,SEQ].
// rowOff: global row offset of this launch's tile grid (batch-half splits).
// ---------------------------------------------------------------------------
#define TILE_BYTES 16384            // 128 rows x 128B
#define STAGE_BYTES (2 * TILE_BYTES)
#define SM_TOTAL (2 * STAGE_BYTES)  // 65536

template <int EPI, bool MULTI_B>
__global__ void __launch_bounds__(256, 2)
gemmh_kernel(const __half* __restrict__ A, const __half* __restrict__ B,
             float* __restrict__ Cf, __half* __restrict__ Ch,
             __half* __restrict__ C1, __half* __restrict__ C2,
             const float* __restrict__ bias,
             int K, int ldC, size_t sA, size_t sB, size_t sC, int rowOff)
{
    extern __shared__ char smem[];
    const uint32_t smem_u = smem_to_u32(smem);
    const int tid = threadIdx.x;
    const int lane = tid & 31;
    const int wid = tid >> 5;
    const int warp_m = wid & 3;
    const int warp_n = wid >> 2;
    const int rowBase = rowOff + blockIdx.y * 128;
    const int colBase = blockIdx.x * 128;
    const size_t zA = MULTI_B ? 0 : (size_t)blockIdx.z * sA;
    const size_t zB = (size_t)blockIdx.z * sB;
    const size_t zC = MULTI_B ? 0 : (size_t)blockIdx.z * sC;
    __half* ChSel = Ch;
    if (MULTI_B) ChSel = (blockIdx.z == 0) ? Ch : ((blockIdx.z == 1) ? C1 : C2);

    const int ldr_row0 = tid >> 3;
    const int ldr_ch   = tid & 7;

    float acc[2][8][4];
#pragma unroll
    for (int i = 0; i < 2; i++)
#pragma unroll
        for (int j = 0; j < 8; j++)
#pragma unroll
            for (int e = 0; e < 4; e++) acc[i][j][e] = 0.0f;

    const int nIter = K >> 6;

    auto issue_load = [&](int i, int stage) {
        const int kk = i << 6;
        const __half* As = A + zA;
        const __half* Bs = B + zB;
        const uint32_t aBase = smem_u + stage * STAGE_BYTES;
        const uint32_t bBase = aBase + TILE_BYTES;
#pragma unroll
        for (int p = 0; p < 4; p++) {
            const int row = ldr_row0 + p * 32;
            const uint32_t soff = SMEM_SWIZZLE_128B((uint32_t)row * 128 + ldr_ch * 16);
            CP_ASYNC_16(aBase + soff,
                        As + (size_t)(rowBase + row) * K + kk + ldr_ch * 8);
            CP_ASYNC_16(bBase + soff,
                        Bs + (size_t)(colBase + row) * K + kk + ldr_ch * 8);
        }
        CP_COMMIT();
    };

    issue_load(0, 0);

    for (int i = 0; i < nIter; i++) {
        const int stage = i & 1;
        if (i + 1 < nIter) {
            issue_load(i + 1, (i + 1) & 1);
            CP_WAIT(1);
        } else {
            CP_WAIT(0);
        }
        __syncthreads();

        const uint32_t aBase = smem_u + stage * STAGE_BYTES;
        const uint32_t bBase = aBase + TILE_BYTES;
#pragma unroll
        for (int ks = 0; ks < 4; ks++) {
            const uint32_t k2 = ks * 32;
            uint32_t a[2][4];
            uint32_t b[4][4];
#pragma unroll
            for (int fm = 0; fm < 2; fm++) {
                const uint32_t row = warp_m * 32 + fm * 16 + (lane & 15);
                const uint32_t addr = aBase +
                    SMEM_SWIZZLE_128B(row * 128 + k2 + ((lane >> 4) << 4));
                LDMATRIX_X4(a[fm][0], a[fm][1], a[fm][2], a[fm][3], addr);
            }
#pragma unroll
            for (int fn2 = 0; fn2 < 4; fn2++) {
                const uint32_t n = warp_n * 64 + fn2 * 16 + (lane & 7) + ((lane >> 4) << 3);
                const uint32_t addr = bBase +
                    SMEM_SWIZZLE_128B(n * 128 + k2 + (((lane >> 3) & 1) << 4));
                LDMATRIX_X4(b[fn2][0], b[fn2][1], b[fn2][2], b[fn2][3], addr);
            }
#pragma unroll
            for (int fn2 = 0; fn2 < 4; fn2++) {
                MMA_F16(acc[0][fn2 * 2 + 0], a[0], b[fn2][0], b[fn2][1]);
                MMA_F16(acc[0][fn2 * 2 + 1], a[0], b[fn2][2], b[fn2][3]);
                MMA_F16(acc[1][fn2 * 2 + 0], a[1], b[fn2][0], b[fn2][1]);
                MMA_F16(acc[1][fn2 * 2 + 1], a[1], b[fn2][2], b[fn2][3]);
            }
        }
        __syncthreads();
    }

    // Epilogue
    const int gid = lane >> 2;
    const int tig = lane & 3;

    if (EPI == 2 && MULTI_B && blockIdx.z == 2) {
        // ---- transposed V output: stage tile in smem, write Vt[d, t] ----
        __half* tsm = reinterpret_cast<__half*>(smem);   // [128][130] fp16
#pragma unroll
        for (int fm = 0; fm < 2; fm++) {
#pragma unroll
            for (int fn = 0; fn < 8; fn++) {
                const int r = warp_m * 32 + fm * 16 + gid;     // tile-local t
                const int c = warp_n * 64 + fn * 8 + tig * 2;  // tile-local d
                const float* ac = acc[fm][fn];
                __half2 h0 = __floats2half2_rn(ac[0], ac[1]);
                __half2 h1 = __floats2half2_rn(ac[2], ac[3]);
                *(__half2*)(&tsm[(size_t)r * 130 + c])       = h0;
                *(__half2*)(&tsm[(size_t)(r + 8) * 130 + c]) = h1;
            }
        }
        __syncthreads();
        const int gRow0 = rowBase;                    // 128-aligned, within one batch
        const size_t bidx = (size_t)gRow0 / SEQ;
        const int tl0 = gRow0 % SEQ;
        __half* dstBase = C2 + bidx * (size_t)DIM * SEQ + tl0;
#pragma unroll 1
        for (int ccb = 0; ccb < 16; ccb++) {
            const int cc = wid * 16 + ccb;            // tile-local d
            __half* drow = dstBase + (size_t)(colBase + cc) * SEQ;
#pragma unroll
            for (int j = 0; j < 4; j++) {
                const int t = lane + 32 * j;
                drow[t] = tsm[(size_t)t * 130 + cc];
            }
        }
        return;
    }

#pragma unroll
    for (int fm = 0; fm < 2; fm++) {
#pragma unroll
        for (int fn = 0; fn < 8; fn++) {
            const int r0 = rowBase + warp_m * 32 + fm * 16 + gid;
            const int c  = colBase + warp_n * 64 + fn * 8 + tig * 2;
            const float* ac = acc[fm][fn];
            if (EPI == 2) {
                __half2 h0 = __floats2half2_rn(ac[0], ac[1]);
                __half2 h1 = __floats2half2_rn(ac[2], ac[3]);
                *(uint32_t*)(ChSel + zC + (size_t)r0 * ldC + c)       = *(uint32_t*)&h0;
                *(uint32_t*)(ChSel + zC + (size_t)(r0 + 8) * ldC + c) = *(uint32_t*)&h1;
            } else if (EPI == 3) {
                // unnormalized attention weights: E = exp2(logit), fp16
                __half2 h0 = __floats2half2_rn(exp2f(ac[0]), exp2f(ac[1]));
                __half2 h1 = __floats2half2_rn(exp2f(ac[2]), exp2f(ac[3]));
                *(uint32_t*)(ChSel + zC + (size_t)r0 * ldC + c)       = *(uint32_t*)&h0;
                *(uint32_t*)(ChSel + zC + (size_t)(r0 + 8) * ldC + c) = *(uint32_t*)&h1;
            } else if (EPI == 4) {
                // PV normalize: multiply each output row by rinv[row]
                const float rs0 = bias[(size_t)blockIdx.z * SEQ + r0];
                const float rs1 = bias[(size_t)blockIdx.z * SEQ + r0 + 8];
                __half2 h0 = __floats2half2_rn(ac[0] * rs0, ac[1] * rs0);
                __half2 h1 = __floats2half2_rn(ac[2] * rs1, ac[3] * rs1);
                *(uint32_t*)(ChSel + zC + (size_t)r0 * ldC + c)       = *(uint32_t*)&h0;
                *(uint32_t*)(ChSel + zC + (size_t)(r0 + 8) * ldC + c) = *(uint32_t*)&h1;
            } else {
                float2 v0 = make_float2(ac[0], ac[1]);
                float2 v1 = make_float2(ac[2], ac[3]);
                if (EPI == 1) {
                    const float b0 = bias[c], b1 = bias[c + 1];
                    v0.x += b0; v0.y += b1;
                    v1.x += b0; v1.y += b1;
                }
                *(float2*)(Cf + zC + (size_t)r0 * ldC + c)       = v0;
                *(float2*)(Cf + zC + (size_t)(r0 + 8) * ldC + c) = v1;
            }
        }
    }
}

// ---------------------------------------------------------------------------
// fp32 -> fp16 convert (elementwise)
// ---------------------------------------------------------------------------
__global__ void __launch_bounds__(256)
convert_fp16_kernel(const float* __restrict__ x, __half* __restrict__ h)
{
    size_t i = ((size_t)blockIdx.x * 256 + threadIdx.x) * 4;
    float4 v = *(const float4*)(x + i);
    __half2 a = __floats2half2_rn(v.x, v.y);
    __half2 b = __floats2half2_rn(v.z, v.w);
    *(uint2*)(h + i) = make_uint2(*(uint32_t*)&a, *(uint32_t*)&b);
}

// ---------------------------------------------------------------------------
// Transpose + convert ALL FOUR weight matrices in one launch.
// Wq (z==0) pre-scaled by scale*log2e -> E = exp2(logit) directly.
// ---------------------------------------------------------------------------
__global__ void __launch_bounds__(256)
transW_all_kernel(const float* __restrict__ W0, const float* __restrict__ W1,
                  const float* __restrict__ W2, const float* __restrict__ W3,
                  __half* __restrict__ thB, float qscale)
{
    const float* W = (blockIdx.z == 0) ? W0 :
                     (blockIdx.z == 1) ? W1 :
                     (blockIdx.z == 2) ? W2 : W3;
    const float sc = (blockIdx.z == 0) ? qscale : 1.0f;
    __half* th = thB + (size_t)blockIdx.z * DIM * DIM;
    __shared__ float t[32][33];
    const int tx = threadIdx.x, ty = threadIdx.y;
    const int x = blockIdx.x * 32 + tx;
    const int y0 = blockIdx.y * 32;
#pragma unroll
    for (int p = 0; p < 4; p++)
        t[ty + 8 * p][tx] = W[(size_t)(y0 + ty + 8 * p) * DIM + x];
    __syncthreads();
    const int ox = blockIdx.y * 32 + tx;
    const int oy0 = blockIdx.x * 32;
#pragma unroll
    for (int p = 0; p < 4; p++)
        th[(size_t)(oy0 + ty + 8 * p) * DIM + ox] =
            __float2half_rn(t[tx][ty + 8 * p] * sc);
}

// ---------------------------------------------------------------------------
// Row-sum of fp16 E rows (SEQ=2048) -> rinv[row] = 1/sum (fp32).
// 256 threads/row, one uint4 (8 halves) per thread.
// ---------------------------------------------------------------------------
__global__ void __launch_bounds__(256)
rowsum_kernel(const __half* __restrict__ E, float* __restrict__ rinv)
{
    const size_t row = blockIdx.x;
    const int tid = threadIdx.x;
    uint4 v = *(const uint4*)(E + row * SEQ + tid * 8);
    const __half2* hp = reinterpret_cast<const __half2*>(&v);
    float s = 0.0f;
#pragma unroll
    for (int j = 0; j < 4; j++) {
        float2 f = __half22float2(hp[j]);
        s += f.x + f.y;
    }
    __shared__ float red[8];
#pragma unroll
    for (int o = 16; o > 0; o >>= 1)
        s += __shfl_xor_sync(0xffffffffu, s, o);
    if ((tid & 31) == 0) red[tid >> 5] = s;
    __syncthreads();
    if (tid == 0) {
        float tot = 0.0f;
#pragma unroll
        for (int w = 0; w < 8; w++) tot += red[w];
        rinv[row] = 1.0f / tot;
    }
}

// ---------------------------------------------------------------------------
// kernel_launch — half-symmetric pipelined schedule, softmax-free:
//   fork0:  s1: transW -> eW   | s2: convert(h0) -> eC0, convert(h1) -> eC1
//   main:   [eW,eC0] QKV(h0) -> evQ0 ; [eC1] QKV(h1) -> evQ1
//           (QKV z==2 epilogue writes Vt directly)
//   s-h:    [evQh] E = exp2(Q K^T) (fp16, EPI3) -> rowsum -> PV*rinv (EPI4)
//           -> outproj(h) -> eJh
//   main:   [eJ1,eJ2] done.
// Streams/events created AND destroyed per call; both streams joined back
// into the origin stream before destruction (capture-legal, memory baseline).
// ---------------------------------------------------------------------------
extern "C" void kernel_launch(void* const* d_in, const int* in_sizes, int n_in,
                              void* d_out, int out_size)
{
    (void)in_sizes; (void)n_in; (void)out_size;
    const float* x  = (const float*)d_in[0];
    const float* Wq = (const float*)d_in[1];
    const float* Wk = (const float*)d_in[2];
    const float* Wv = (const float*)d_in[3];
    const float* Wp = (const float*)d_in[4];
    const float* bp = (const float*)d_in[5];
    float* out = (float*)d_out;

    __half *xH, *WtH, *Q, *K, *Vt, *O, *E;
    float* Rinv;
    cudaGetSymbolAddress((void**)&xH, g_xH);
    cudaGetSymbolAddress((void**)&WtH, g_WtH);
    cudaGetSymbolAddress((void**)&Q, g_Q);
    cudaGetSymbolAddress((void**)&K, g_K);
    cudaGetSymbolAddress((void**)&Vt, g_Vt);
    cudaGetSymbolAddress((void**)&O, g_O);
    cudaGetSymbolAddress((void**)&E, g_E);
    cudaGetSymbolAddress((void**)&Rinv, g_Rinv);

    const size_t wstep = (size_t)DIM * DIM;

    cudaFuncSetAttribute(gemmh_kernel<1, false>, cudaFuncAttributeMaxDynamicSharedMemorySize, SM_TOTAL);
    cudaFuncSetAttribute(gemmh_kernel<2, true>,  cudaFuncAttributeMaxDynamicSharedMemorySize, SM_TOTAL);
    cudaFuncSetAttribute(gemmh_kernel<3, false>, cudaFuncAttributeMaxDynamicSharedMemorySize, SM_TOTAL);
    cudaFuncSetAttribute(gemmh_kernel<4, false>, cudaFuncAttributeMaxDynamicSharedMemorySize, SM_TOTAL);

    // Fork plumbing — created per call, destroyed at the end of this call.
    cudaStream_t s1, s2;
    cudaEvent_t evF, eW, eC0, eC1, evQ0, evQ1, eJ1, eJ2;
    cudaStreamCreateWithFlags(&s1, cudaStreamNonBlocking);
    cudaStreamCreateWithFlags(&s2, cudaStreamNonBlocking);
    cudaEventCreateWithFlags(&evF, cudaEventDisableTiming);
    cudaEventCreateWithFlags(&eW,  cudaEventDisableTiming);
    cudaEventCreateWithFlags(&eC0, cudaEventDisableTiming);
    cudaEventCreateWithFlags(&eC1, cudaEventDisableTiming);
    cudaEventCreateWithFlags(&evQ0, cudaEventDisableTiming);
    cudaEventCreateWithFlags(&evQ1, cudaEventDisableTiming);
    cudaEventCreateWithFlags(&eJ1, cudaEventDisableTiming);
    cudaEventCreateWithFlags(&eJ2, cudaEventDisableTiming);

    const size_t HB = 4;                       // batches per half
    const size_t HROWS = HB * SEQ;             // rows per half (8192)
    const size_t qkvOff = HROWS * DIM;         // fp16 elements per half
    const size_t sOff   = HB * SEQ * SEQ;      // E elements per half

    // ---- fork 0: prep ----
    cudaEventRecord(evF, 0);
    cudaStreamWaitEvent(s1, evF, 0);
    cudaStreamWaitEvent(s2, evF, 0);
    {
        dim3 g(DIM / 32, DIM / 32, 4), b(32, 8);
        transW_all_kernel<<<g, b, 0, s1>>>(Wq, Wk, Wv, Wp, WtH,
                                           0.03125f * 1.4426950408889634f);
    }
    cudaEventRecord(eW, s1);
    convert_fp16_kernel<<<qkvOff / 1024, 256, 0, s2>>>(x, xH);
    cudaEventRecord(eC0, s2);
    convert_fp16_kernel<<<qkvOff / 1024, 256, 0, s2>>>(x + qkvOff, xH + qkvOff);
    cudaEventRecord(eC1, s2);

    // ---- main: QKV by halves (z==2 writes Vt transposed in-epilogue) ----
    cudaStreamWaitEvent(0, eW, 0);
    cudaStreamWaitEvent(0, eC0, 0);
    {
        dim3 g(DIM / 128, HROWS / 128, 3);
        gemmh_kernel<2, true><<<g, 256, SM_TOTAL>>>(
            xH, WtH, nullptr, Q, K, Vt, nullptr,
            DIM, DIM, 0, wstep, 0, 0);
    }
    cudaEventRecord(evQ0, 0);
    cudaStreamWaitEvent(0, eC1, 0);
    {
        dim3 g(DIM / 128, HROWS / 128, 3);
        gemmh_kernel<2, true><<<g, 256, SM_TOTAL>>>(
            xH, WtH, nullptr, Q, K, Vt, nullptr,
            DIM, DIM, 0, wstep, 0, (int)HROWS);
    }
    cudaEventRecord(evQ1, 0);

    // ---- attention half-chains (no cross-half dependencies) ----
    for (int h = 0; h < 2; h++) {
        cudaStream_t st = h ? s2 : s1;
        cudaStreamWaitEvent(st, h ? evQ1 : evQ0, 0);
        const size_t qo = h * qkvOff;
        const size_t so = h * sOff;
        float* rinvH = Rinv + h * HROWS;

        {   // E = exp2(Q K^T) (4 batches, fp16 unnormalized weights)
            dim3 g(SEQ / 128, SEQ / 128, HB);
            gemmh_kernel<3, false><<<g, 256, SM_TOTAL, st>>>(
                Q + qo, K + qo, nullptr, E + so, nullptr, nullptr, nullptr,
                DIM, SEQ,
                (size_t)SEQ * DIM, (size_t)SEQ * DIM, (size_t)SEQ * SEQ, 0);
        }
        rowsum_kernel<<<HROWS, 256, 0, st>>>(E + so, rinvH);
        {   // O = (E @ V) * rinv[row]  (B = Vt, per-batch [DIM, SEQ])
            dim3 g(DIM / 128, SEQ / 128, HB);
            gemmh_kernel<4, false><<<g, 256, SM_TOTAL, st>>>(
                E + so, Vt + qo, nullptr, O + qo, nullptr, nullptr, rinvH,
                SEQ, DIM,
                (size_t)SEQ * SEQ, (size_t)DIM * SEQ, (size_t)SEQ * DIM, 0);
        }
        {   // out = O @ Wp^T + bp (this half's rows)
            dim3 g(DIM / 128, HROWS / 128, 1);
            gemmh_kernel<1, false><<<g, 256, SM_TOTAL, st>>>(
                O + qo, WtH + 3 * wstep, out + qo, nullptr, nullptr, nullptr, bp,
                DIM, DIM, 0, 0, 0, 0);
        }
        cudaEventRecord(h ? eJ2 : eJ1, st);
    }

    // ---- join back into origin stream ----
    cudaStreamWaitEvent(0, eJ1, 0);
    cudaStreamWaitEvent(0, eJ2, 0);

    // ---- teardown (streams joined -> out of capture; memory to baseline) ----
    cudaEventDestroy(evF);
    cudaEventDestroy(eW);
    cudaEventDestroy(eC0);
    cudaEventDestroy(eC1);
    cudaEventDestroy(evQ0);
    cudaEventDestroy(evQ1);
    cudaEventDestroy(eJ1);
    cudaEventDestroy(eJ2);
    cudaStreamDestroy(s1);
    cudaStreamDestroy(s2);
}